// round 2
// baseline (speedup 1.0000x reference)
#include <cuda_runtime.h>
#include <math.h>

#define NTOK 8192
#define DIM  1024
#define NEXP 8
#define HID  4096
#define CAP  1024

// ---------------- scratch (static __device__, no allocs) ----------------
__device__ float g_xbuf[(size_t)NEXP * CAP * DIM];   // gathered tokens
__device__ float g_hbuf[(size_t)NEXP * CAP * HID];   // hidden activations
__device__ float g_obuf[(size_t)NEXP * CAP * DIM];   // expert outputs
__device__ float g_probs[(size_t)NTOK * NEXP];
__device__ float g_lse2[NTOK];
__device__ float g_eprob[NTOK];
__device__ int   g_eidx[NTOK];
__device__ int   g_slot[NTOK];          // slot within expert, -1 if dropped
__device__ int   g_sortidx[NTOK];       // sort_idx[sorted_pos] = token
__device__ int   g_tok_of_slot[NEXP * CAP];
__device__ int   g_counts[NEXP];
__device__ int   g_start[NEXP];

// ---------------- init ----------------
__global__ void init_kernel() {
    int t = threadIdx.x;
    if (t < NEXP) g_counts[t] = 0;
}

// ---------------- router: logits, softmax, argmax, per-token stats ----------------
__global__ void router_kernel(const float* __restrict__ x,
                              const float* __restrict__ Wg) {
    int n = blockIdx.x;
    int tid = threadIdx.x;               // 128 threads
    float acc[NEXP];
#pragma unroll
    for (int e = 0; e < NEXP; e++) acc[e] = 0.f;
    const float* xr = x + (size_t)n * DIM;
    for (int d = tid; d < DIM; d += 128) {
        float xv = xr[d];
        const float* w = Wg + (size_t)d * NEXP;
#pragma unroll
        for (int e = 0; e < NEXP; e++) acc[e] += xv * w[e];
    }
    __shared__ float sm[NEXP][128];
#pragma unroll
    for (int e = 0; e < NEXP; e++) sm[e][tid] = acc[e];
    __syncthreads();
    for (int off = 64; off > 0; off >>= 1) {
        if (tid < off) {
#pragma unroll
            for (int e = 0; e < NEXP; e++) sm[e][tid] += sm[e][tid + off];
        }
        __syncthreads();
    }
    if (tid == 0) {
        float l[NEXP];
#pragma unroll
        for (int e = 0; e < NEXP; e++) l[e] = sm[e][0];
        float m = l[0]; int bi = 0;
#pragma unroll
        for (int e = 1; e < NEXP; e++) { if (l[e] > m) { m = l[e]; bi = e; } }
        float p[NEXP]; float s = 0.f;
#pragma unroll
        for (int e = 0; e < NEXP; e++) { p[e] = expf(l[e] - m); s += p[e]; }
        float inv = 1.f / s;
#pragma unroll
        for (int e = 0; e < NEXP; e++) { p[e] *= inv; g_probs[(size_t)n * NEXP + e] = p[e]; }
        float lse = m + logf(s);
        g_lse2[n]  = lse * lse;
        g_eidx[n]  = bi;
        g_eprob[n] = p[bi];
        atomicAdd(&g_counts[bi], 1);
    }
}

// ---------------- deterministic reduce: aux loss + start offsets ----------------
__global__ void reduce_kernel(float* aux_out) {
    int tid = threadIdx.x;               // 256 threads
    float z = 0.f; float p[NEXP];
#pragma unroll
    for (int e = 0; e < NEXP; e++) p[e] = 0.f;
    for (int n = tid; n < NTOK; n += 256) {
        z += g_lse2[n];
#pragma unroll
        for (int e = 0; e < NEXP; e++) p[e] += g_probs[(size_t)n * NEXP + e];
    }
    __shared__ float sz[256];
    __shared__ float sp[NEXP][256];
    sz[tid] = z;
#pragma unroll
    for (int e = 0; e < NEXP; e++) sp[e][tid] = p[e];
    __syncthreads();
    for (int off = 128; off > 0; off >>= 1) {
        if (tid < off) {
            sz[tid] += sz[tid + off];
#pragma unroll
            for (int e = 0; e < NEXP; e++) sp[e][tid] += sp[e][tid + off];
        }
        __syncthreads();
    }
    if (tid == 0) {
        float zloss = sz[0] / (float)NTOK;
        float dot = 0.f; int run = 0;
#pragma unroll
        for (int e = 0; e < NEXP; e++) {
            float fi = (float)g_counts[e] / (float)NTOK;
            float pi = sp[e][0] / (float)NTOK;
            dot += fi * pi;
            g_start[e] = run;
            run += g_counts[e];
        }
        float aux = 0.01f * (float)NEXP * dot + 0.001f * zloss;
        if (aux_out) *aux_out = aux;
    }
}

// ---------------- stable per-expert ranks (reproduces stable argsort) ----------------
__global__ void pos_kernel() {           // grid NEXP, block 1024
    int e = blockIdx.x;
    int tid = threadIdx.x;
    int lane = tid & 31, wid = tid >> 5;
    __shared__ int wsum[32];
    __shared__ int wbase[32];
    __shared__ int sbase;
    if (tid == 0) sbase = 0;
    __syncthreads();
    for (int n0 = 0; n0 < NTOK; n0 += 1024) {
        int n = n0 + tid;
        bool pred = (g_eidx[n] == e);
        unsigned b = __ballot_sync(0xffffffffu, pred);
        int wpre = __popc(b & ((1u << lane) - 1u));
        if (lane == 0) wsum[wid] = __popc(b);
        __syncthreads();
        if (tid == 0) {
            int r = sbase;
#pragma unroll
            for (int w = 0; w < 32; w++) { wbase[w] = r; r += wsum[w]; }
            sbase = r;
        }
        __syncthreads();
        if (pred) {
            int pos  = wbase[wid] + wpre;
            int spos = g_start[e] + pos;
            g_sortidx[spos] = n;
            if (pos < CAP) {
                g_slot[n] = pos;
                g_tok_of_slot[e * CAP + pos] = n;
            } else {
                g_slot[n] = -1;
            }
        }
        __syncthreads();
    }
}

// ---------------- gather tokens into per-expert buffers ----------------
__global__ void gather_kernel(const float* __restrict__ x) {
    int row = blockIdx.x;                // [0, NEXP*CAP)
    int e = row / CAP;
    int slot = row - e * CAP;
    int rows_e = min(g_counts[e], CAP);
    if (slot >= rows_e) return;
    int n = g_tok_of_slot[row];
    const float4* src = (const float4*)(x + (size_t)n * DIM);
    float4* dst = (float4*)(g_xbuf + (size_t)row * DIM);
    for (int i = threadIdx.x; i < DIM / 4; i += 256) dst[i] = src[i];
}

// ---------------- fp32 GEMM with packed f32x2 FFMA ----------------
#define BM 128
#define BN 128
#define BK 16

__device__ __forceinline__ long long pack2(float lo, float hi) {
    long long r;
    asm("mov.b64 %0, {%1,%2};" : "=l"(r) : "f"(lo), "f"(hi));
    return r;
}
__device__ __forceinline__ void unpack2(long long v, float& lo, float& hi) {
    asm("mov.b64 {%0,%1}, %2;" : "=f"(lo), "=f"(hi) : "l"(v));
}
#define FFMA2(d, a, b) asm("fma.rn.f32x2 %0, %1, %2, %0;" : "+l"(d) : "l"(a), "l"(b))

template <bool GELU>
__device__ __forceinline__ void gemm_tile(const float* __restrict__ A,
                                          const float* __restrict__ Bw,
                                          const float* __restrict__ bias,
                                          float* __restrict__ C,
                                          int N, int K) {
    __shared__ float As[BK][BM + 4];     // row = 132 floats = 528B (16B multiple)
    __shared__ float Bs[BK][BN];
    int tid = threadIdx.x;               // 256 threads
    int tx = tid & 15, ty = tid >> 4;
    int row0 = blockIdx.y * BM;
    int col0 = blockIdx.x * BN;

    long long acc[8][4];
#pragma unroll
    for (int r = 0; r < 8; r++)
#pragma unroll
        for (int c = 0; c < 4; c++) acc[r][c] = 0LL;  // bits of (+0,+0)

    for (int k0 = 0; k0 < K; k0 += BK) {
#pragma unroll
        for (int i = 0; i < 2; i++) {    // A tile: 128x16, transposed store
            int f = i * 256 + tid;
            int r = f >> 2, c4 = f & 3;
            float4 v = *(const float4*)(A + (size_t)(row0 + r) * K + k0 + c4 * 4);
            As[c4 * 4 + 0][r] = v.x;
            As[c4 * 4 + 1][r] = v.y;
            As[c4 * 4 + 2][r] = v.z;
            As[c4 * 4 + 3][r] = v.w;
        }
#pragma unroll
        for (int i = 0; i < 2; i++) {    // B tile: 16x128
            int f = i * 256 + tid;
            int r = f >> 5, c4 = f & 31;
            *(float4*)&Bs[r][c4 * 4] =
                *(const float4*)(Bw + (size_t)(k0 + r) * N + col0 + c4 * 4);
        }
        __syncthreads();
#pragma unroll
        for (int kk = 0; kk < BK; kk++) {
            float4 b0 = *(float4*)&Bs[kk][tx * 8];
            float4 b1 = *(float4*)&Bs[kk][tx * 8 + 4];
            long long bp0 = pack2(b0.x, b0.y), bp1 = pack2(b0.z, b0.w);
            long long bp2 = pack2(b1.x, b1.y), bp3 = pack2(b1.z, b1.w);
            float4 a0 = *(float4*)&As[kk][ty * 8];
            float4 a1 = *(float4*)&As[kk][ty * 8 + 4];
            float ar[8] = {a0.x, a0.y, a0.z, a0.w, a1.x, a1.y, a1.z, a1.w};
#pragma unroll
            for (int r = 0; r < 8; r++) {
                long long ap = pack2(ar[r], ar[r]);
                FFMA2(acc[r][0], ap, bp0);
                FFMA2(acc[r][1], ap, bp1);
                FFMA2(acc[r][2], ap, bp2);
                FFMA2(acc[r][3], ap, bp3);
            }
        }
        __syncthreads();
    }
    // epilogue
#pragma unroll
    for (int r = 0; r < 8; r++) {
        int row = row0 + ty * 8 + r;
        int col = col0 + tx * 8;
        float v[8];
#pragma unroll
        for (int c = 0; c < 4; c++) unpack2(acc[r][c], v[2 * c], v[2 * c + 1]);
#pragma unroll
        for (int j = 0; j < 8; j++) {
            float t = v[j] + bias[col + j];
            if (GELU) t = 0.5f * t * (1.0f + erff(t * 0.70710678118654752f));
            v[j] = t;
        }
        float4* dst = (float4*)(C + (size_t)row * N + col);
        dst[0] = make_float4(v[0], v[1], v[2], v[3]);
        dst[1] = make_float4(v[4], v[5], v[6], v[7]);
    }
}

__global__ __launch_bounds__(256) void gemm1_kernel(const float* __restrict__ W1,
                                                    const float* __restrict__ b1) {
    int e = blockIdx.z;
    gemm_tile<true>(g_xbuf + (size_t)e * CAP * DIM,
                    W1 + (size_t)e * DIM * HID,
                    b1 + (size_t)e * HID,
                    g_hbuf + (size_t)e * CAP * HID,
                    HID, DIM);
}

__global__ __launch_bounds__(256) void gemm2_kernel(const float* __restrict__ W2,
                                                    const float* __restrict__ b2) {
    int e = blockIdx.z;
    gemm_tile<false>(g_hbuf + (size_t)e * CAP * HID,
                     W2 + (size_t)e * HID * DIM,
                     b2 + (size_t)e * DIM,
                     g_obuf + (size_t)e * CAP * DIM,
                     DIM, HID);
}

// ---------------- combine: unsort + quirky prob scaling ----------------
// final[n] = (kept ? o[e_n, slot_n] : 0) * expert_prob[sort_idx[n]]
__global__ void combine_kernel(float* __restrict__ out) {
    int n = blockIdx.x;
    int m = g_sortidx[n];
    float scale = g_eprob[m];
    int slot = g_slot[n];
    float4* dst = (float4*)(out + (size_t)n * DIM);
    if (slot < 0) {
        float4 z = make_float4(0.f, 0.f, 0.f, 0.f);
        for (int i = threadIdx.x; i < DIM / 4; i += 256) dst[i] = z;
        return;
    }
    int e = g_eidx[n];
    const float4* src = (const float4*)(g_obuf + (size_t)(e * CAP + slot) * DIM);
    for (int i = threadIdx.x; i < DIM / 4; i += 256) {
        float4 v = src[i];
        dst[i] = make_float4(v.x * scale, v.y * scale, v.z * scale, v.w * scale);
    }
}

// ---------------- launch ----------------
extern "C" void kernel_launch(void* const* d_in, const int* in_sizes, int n_in,
                              void* d_out, int out_size) {
    const float* x  = (const float*)d_in[0];
    const float* Wg = (const float*)d_in[1];
    const float* W1 = (const float*)d_in[2];
    const float* b1 = (const float*)d_in[3];
    const float* W2 = (const float*)d_in[4];
    const float* b2 = (const float*)d_in[5];
    float* out = (float*)d_out;
    float* aux_out = (out_size > NTOK * DIM) ? (out + (size_t)NTOK * DIM) : nullptr;

    init_kernel<<<1, 32>>>();
    router_kernel<<<NTOK, 128>>>(x, Wg);
    reduce_kernel<<<1, 256>>>(aux_out);
    pos_kernel<<<NEXP, 1024>>>();
    gather_kernel<<<NEXP * CAP, 256>>>(x);

    dim3 g1(HID / BN, CAP / BM, NEXP);   // 32 x 8 x 8
    gemm1_kernel<<<g1, 256>>>(W1, b1);
    dim3 g2(DIM / BN, CAP / BM, NEXP);   // 8 x 8 x 8
    gemm2_kernel<<<g2, 256>>>(W2, b2);

    combine_kernel<<<NTOK, 256>>>(out);
}

// round 4
// speedup vs baseline: 2.1451x; 2.1451x over previous
#include <cuda_runtime.h>
#include <cuda_bf16.h>
#include <math.h>
#include <stdint.h>

#define NTOK 8192
#define DIM  1024
#define NEXP 8
#define HID  4096
#define CAP  1024

// ================= scratch =================
__device__ __nv_bfloat16 g_x_hi[(size_t)NTOK * DIM];
__device__ __nv_bfloat16 g_x_lo[(size_t)NTOK * DIM];
__device__ __nv_bfloat16 g_h_hi[(size_t)NTOK * HID];
__device__ __nv_bfloat16 g_h_lo[(size_t)NTOK * HID];
__device__ float         g_obuf[(size_t)NTOK * DIM];
__device__ __nv_bfloat16 g_w1_hi[(size_t)NEXP * HID * DIM];  // [E][H][D]
__device__ __nv_bfloat16 g_w1_lo[(size_t)NEXP * HID * DIM];
__device__ __nv_bfloat16 g_w2_hi[(size_t)NEXP * DIM * HID];  // [E][D][H]
__device__ __nv_bfloat16 g_w2_lo[(size_t)NEXP * DIM * HID];
__device__ float g_probs[(size_t)NTOK * NEXP];
__device__ float g_lse2[NTOK];
__device__ float g_eprob[NTOK];
__device__ int   g_eidx[NTOK];
__device__ int   g_slot[NTOK];
__device__ int   g_sortidx[NTOK];
__device__ int   g_tok_of_slot[NEXP * CAP];
__device__ int   g_counts[NEXP];
__device__ int   g_start[NEXP];

__device__ __forceinline__ void split2(float v, __nv_bfloat16& h, __nv_bfloat16& l) {
    h = __float2bfloat16_rn(v);
    l = __float2bfloat16_rn(v - __bfloat162float(h));
}
__device__ __forceinline__ uint32_t pack_bf(__nv_bfloat16 a, __nv_bfloat16 b) {
    return ((uint32_t)__bfloat16_as_ushort(b) << 16) | (uint32_t)__bfloat16_as_ushort(a);
}
__device__ __forceinline__ uint32_t smem_u32(const void* p) {
    uint32_t a;
    asm("{ .reg .u64 t; cvta.to.shared.u64 t, %1; cvt.u32.u64 %0, t; }" : "=r"(a) : "l"(p));
    return a;
}

// ---- PTX: mma / ldmatrix / cp.async (valid on plain compute_103) ----
__device__ __forceinline__ void mma16816(float* c, const uint32_t* a, const uint32_t* b) {
    asm volatile("mma.sync.aligned.m16n8k16.row.col.f32.bf16.bf16.f32 "
                 "{%0,%1,%2,%3}, {%4,%5,%6,%7}, {%8,%9}, {%0,%1,%2,%3};"
                 : "+f"(c[0]), "+f"(c[1]), "+f"(c[2]), "+f"(c[3])
                 : "r"(a[0]), "r"(a[1]), "r"(a[2]), "r"(a[3]), "r"(b[0]), "r"(b[1]));
}
#define LDSM4(r0, r1, r2, r3, a) \
    asm volatile("ldmatrix.sync.aligned.m8n8.x4.shared.b16 {%0,%1,%2,%3}, [%4];" \
                 : "=r"(r0), "=r"(r1), "=r"(r2), "=r"(r3) : "r"(a))
__device__ __forceinline__ void cp_async16(uint32_t saddr, const void* gptr) {
    asm volatile("cp.async.cg.shared.global [%0], [%1], 16;" :: "r"(saddr), "l"(gptr));
}
#define CP_COMMIT() asm volatile("cp.async.commit_group;" ::: "memory")
#define CP_WAIT1()  asm volatile("cp.async.wait_group 1;" ::: "memory")

// ================= init =================
__global__ void init_kernel() {
    if (threadIdx.x < NEXP) g_counts[threadIdx.x] = 0;
}

// ================= router =================
__global__ void router_kernel(const float* __restrict__ x, const float* __restrict__ Wg) {
    int n = blockIdx.x, tid = threadIdx.x;  // 128 threads
    float acc[NEXP];
#pragma unroll
    for (int e = 0; e < NEXP; e++) acc[e] = 0.f;
    const float* xr = x + (size_t)n * DIM;
    for (int d = tid; d < DIM; d += 128) {
        float xv = xr[d];
        const float* w = Wg + (size_t)d * NEXP;
#pragma unroll
        for (int e = 0; e < NEXP; e++) acc[e] += xv * w[e];
    }
    __shared__ float sm[NEXP][128];
#pragma unroll
    for (int e = 0; e < NEXP; e++) sm[e][tid] = acc[e];
    __syncthreads();
    for (int off = 64; off > 0; off >>= 1) {
        if (tid < off)
#pragma unroll
            for (int e = 0; e < NEXP; e++) sm[e][tid] += sm[e][tid + off];
        __syncthreads();
    }
    if (tid == 0) {
        float l[NEXP];
#pragma unroll
        for (int e = 0; e < NEXP; e++) l[e] = sm[e][0];
        float m = l[0]; int bi = 0;
#pragma unroll
        for (int e = 1; e < NEXP; e++) if (l[e] > m) { m = l[e]; bi = e; }
        float p[NEXP], s = 0.f;
#pragma unroll
        for (int e = 0; e < NEXP; e++) { p[e] = expf(l[e] - m); s += p[e]; }
        float inv = 1.f / s;
#pragma unroll
        for (int e = 0; e < NEXP; e++) { p[e] *= inv; g_probs[(size_t)n * NEXP + e] = p[e]; }
        float lse = m + logf(s);
        g_lse2[n] = lse * lse;
        g_eidx[n] = bi;
        g_eprob[n] = p[bi];
        atomicAdd(&g_counts[bi], 1);
    }
}

// ================= reduce =================
__global__ void reduce_kernel(float* aux_out) {
    int tid = threadIdx.x;  // 256
    float z = 0.f, p[NEXP];
#pragma unroll
    for (int e = 0; e < NEXP; e++) p[e] = 0.f;
    for (int n = tid; n < NTOK; n += 256) {
        z += g_lse2[n];
#pragma unroll
        for (int e = 0; e < NEXP; e++) p[e] += g_probs[(size_t)n * NEXP + e];
    }
    __shared__ float sz[256];
    __shared__ float sp[NEXP][256];
    sz[tid] = z;
#pragma unroll
    for (int e = 0; e < NEXP; e++) sp[e][tid] = p[e];
    __syncthreads();
    for (int off = 128; off > 0; off >>= 1) {
        if (tid < off) {
            sz[tid] += sz[tid + off];
#pragma unroll
            for (int e = 0; e < NEXP; e++) sp[e][tid] += sp[e][tid + off];
        }
        __syncthreads();
    }
    if (tid == 0) {
        float zloss = sz[0] / (float)NTOK;
        float dot = 0.f; int run = 0;
#pragma unroll
        for (int e = 0; e < NEXP; e++) {
            float fi = (float)g_counts[e] / (float)NTOK;
            float pi = sp[e][0] / (float)NTOK;
            dot += fi * pi;
            g_start[e] = run;
            run += g_counts[e];
        }
        if (aux_out) *aux_out = 0.01f * (float)NEXP * dot + 0.001f * zloss;
    }
}

// ================= stable per-expert ranks =================
__global__ void pos_kernel() {
    int e = blockIdx.x, tid = threadIdx.x;
    int lane = tid & 31, wid = tid >> 5;
    __shared__ int wsum[32], wbase[32], sbase;
    if (tid == 0) sbase = 0;
    __syncthreads();
    for (int n0 = 0; n0 < NTOK; n0 += 1024) {
        int n = n0 + tid;
        bool pred = (g_eidx[n] == e);
        unsigned b = __ballot_sync(0xffffffffu, pred);
        int wpre = __popc(b & ((1u << lane) - 1u));
        if (lane == 0) wsum[wid] = __popc(b);
        __syncthreads();
        if (tid == 0) {
            int r = sbase;
#pragma unroll
            for (int w = 0; w < 32; w++) { wbase[w] = r; r += wsum[w]; }
            sbase = r;
        }
        __syncthreads();
        if (pred) {
            int pos = wbase[wid] + wpre;
            g_sortidx[g_start[e] + pos] = n;
            if (pos < CAP) { g_slot[n] = pos; g_tok_of_slot[e * CAP + pos] = n; }
            else g_slot[n] = -1;
        }
        __syncthreads();
    }
}

// ================= gather + bf16 split =================
__global__ void gather_kernel(const float* __restrict__ x) {
    int row = blockIdx.x;
    int e = row >> 10;
    int slot = row & (CAP - 1);
    if (slot >= min(g_counts[e], CAP)) return;
    int n = g_tok_of_slot[row];
    const float4* src = (const float4*)(x + (size_t)n * DIM);
    uint2* dh = (uint2*)(g_x_hi + (size_t)row * DIM);
    uint2* dl = (uint2*)(g_x_lo + (size_t)row * DIM);
    for (int i = threadIdx.x; i < DIM / 4; i += 256) {
        float4 v = src[i];
        __nv_bfloat16 h0,l0,h1,l1,h2,l2,h3,l3;
        split2(v.x,h0,l0); split2(v.y,h1,l1); split2(v.z,h2,l2); split2(v.w,h3,l3);
        dh[i] = make_uint2(pack_bf(h0,h1), pack_bf(h2,h3));
        dl[i] = make_uint2(pack_bf(l0,l1), pack_bf(l2,l3));
    }
}

// ================= transpose + bf16 split weights =================
__global__ void transconv_kernel(const float* __restrict__ src,
                                 __nv_bfloat16* __restrict__ dh,
                                 __nv_bfloat16* __restrict__ dl,
                                 int K, int N) {
    __shared__ float t[32][33];
    int e = blockIdx.z;
    const float* s = src + (size_t)e * K * N;
    __nv_bfloat16* oh = dh + (size_t)e * N * K;
    __nv_bfloat16* ol = dl + (size_t)e * N * K;
    int n0 = blockIdx.x * 32, k0 = blockIdx.y * 32;
    int tx = threadIdx.x, ty = threadIdx.y;
#pragma unroll
    for (int i = ty; i < 32; i += 8)
        t[i][tx] = s[(size_t)(k0 + i) * N + n0 + tx];
    __syncthreads();
#pragma unroll
    for (int i = ty; i < 32; i += 8) {
        float v = t[tx][i];
        __nv_bfloat16 h, l; split2(v, h, l);
        size_t o = (size_t)(n0 + i) * K + k0 + tx;
        oh[o] = h; ol[o] = l;
    }
}

// ================= HMMA bf16x3 grouped GEMM =================
#define ROWB   80
#define OFF_AH 0
#define OFF_AL 10240
#define OFF_BH 20480
#define OFF_BL 30720
#define ST_SZ  40960
#define GEMM_SMEM (2 * ST_SZ)

template <bool GELU, int K, int NTOT>
__global__ __launch_bounds__(256) void gemm_kernel(
    const __nv_bfloat16* __restrict__ Agh, const __nv_bfloat16* __restrict__ Agl,
    const __nv_bfloat16* __restrict__ Bgh, const __nv_bfloat16* __restrict__ Bgl,
    const float* __restrict__ bias_g,
    __nv_bfloat16* __restrict__ outh, __nv_bfloat16* __restrict__ outl,
    float* __restrict__ outf)
{
    extern __shared__ __align__(128) char smem[];
    const uint32_t sbase = smem_u32(smem);
    const int tid  = threadIdx.x;
    const int wid  = tid >> 5;
    const int lane = tid & 31;
    const int wm   = wid & 3;
    const int wn   = wid >> 2;

    const int e    = blockIdx.z;
    const int row0 = blockIdx.y * 128;          // expert-local row
    const int col0 = blockIdx.x * 128;

    const __nv_bfloat16* Ah = Agh + (size_t)e * CAP * K + (size_t)row0 * K;
    const __nv_bfloat16* Al = Agl + (size_t)e * CAP * K + (size_t)row0 * K;
    const __nv_bfloat16* Bh = Bgh + (size_t)e * NTOT * K + (size_t)col0 * K;
    const __nv_bfloat16* Bl = Bgl + (size_t)e * NTOT * K + (size_t)col0 * K;
    const float* bias = bias_g + (size_t)e * NTOT + col0;
    const size_t orow0 = (size_t)e * CAP + row0;   // global output row base

    const __nv_bfloat16* srcs[4] = {Ah, Al, Bh, Bl};

    float acc[2][8][4];
#pragma unroll
    for (int mt = 0; mt < 2; mt++)
#pragma unroll
        for (int nt = 0; nt < 8; nt++)
#pragma unroll
            for (int q = 0; q < 4; q++) acc[mt][nt][q] = 0.f;

    const uint32_t aOff = (uint32_t)((wm * 32 + (lane & 15)) * ROWB + ((lane >> 4) * 8) * 2);
    const uint32_t bOff = (uint32_t)((wn * 64 + ((lane >> 4) * 8) + (lane & 7)) * ROWB
                                     + (((lane >> 3) & 1) * 8) * 2);

    auto prefetch = [&](int c, int stage) {
        const int k0 = c * 32;
        const uint32_t sb = sbase + stage * ST_SZ;
#pragma unroll
        for (int ii = 0; ii < 8; ii++) {
            int i = ii * 256 + tid;
            int arr = i >> 9;
            int idx = i & 511;
            int r = idx >> 2, s = idx & 3;
            const __nv_bfloat16* g = srcs[arr] + (size_t)r * K + k0 + s * 8;
            cp_async16(sb + (uint32_t)(arr * 10240 + r * ROWB + s * 16), g);
        }
    };

    prefetch(0, 0);
    CP_COMMIT();

    const int NC = K / 32;
    int stage = 0;
    for (int c = 0; c < NC; c++) {
        if (c + 1 < NC) prefetch(c + 1, stage ^ 1);
        CP_COMMIT();
        CP_WAIT1();
        __syncthreads();

        const uint32_t sb = sbase + stage * ST_SZ;
#pragma unroll
        for (int kk = 0; kk < 2; kk++) {
            const uint32_t kByte = (uint32_t)(kk * 32);
            uint32_t ah[2][4], al[2][4];
#pragma unroll
            for (int mt = 0; mt < 2; mt++) {
                uint32_t addr = sb + aOff + (uint32_t)(mt * 16 * ROWB) + kByte;
                LDSM4(ah[mt][0], ah[mt][1], ah[mt][2], ah[mt][3], addr + OFF_AH);
                LDSM4(al[mt][0], al[mt][1], al[mt][2], al[mt][3], addr + OFF_AL);
            }
            uint32_t bh[8][2], bl[8][2];
#pragma unroll
            for (int bt = 0; bt < 4; bt++) {
                uint32_t addr = sb + bOff + (uint32_t)(bt * 16 * ROWB) + kByte;
                uint32_t r0, r1, r2, r3;
                LDSM4(r0, r1, r2, r3, addr + OFF_BH);
                bh[2*bt][0] = r0; bh[2*bt][1] = r1; bh[2*bt+1][0] = r2; bh[2*bt+1][1] = r3;
                LDSM4(r0, r1, r2, r3, addr + OFF_BL);
                bl[2*bt][0] = r0; bl[2*bt][1] = r1; bl[2*bt+1][0] = r2; bl[2*bt+1][1] = r3;
            }
#pragma unroll
            for (int mt = 0; mt < 2; mt++)
#pragma unroll
                for (int nt = 0; nt < 8; nt++) {
                    mma16816(acc[mt][nt], ah[mt], bh[nt]);
                    mma16816(acc[mt][nt], al[mt], bh[nt]);
                    mma16816(acc[mt][nt], ah[mt], bl[nt]);
                }
        }
        __syncthreads();
        stage ^= 1;
    }

    // ---- epilogue: bias (+ GELU), store ----
    const int lrow = lane >> 2;
    const int lcol = (lane & 3) * 2;
#pragma unroll
    for (int mt = 0; mt < 2; mt++) {
#pragma unroll
        for (int half = 0; half < 2; half++) {
            size_t grow = orow0 + wm * 32 + mt * 16 + half * 8 + lrow;
#pragma unroll
            for (int nt = 0; nt < 8; nt++) {
                int bc = wn * 64 + nt * 8 + lcol;
                int gcol = col0 + bc;
                float v0 = acc[mt][nt][half * 2 + 0] + bias[bc];
                float v1 = acc[mt][nt][half * 2 + 1] + bias[bc + 1];
                if (GELU) {
                    v0 = 0.5f * v0 * (1.0f + erff(v0 * 0.70710678118654752f));
                    v1 = 0.5f * v1 * (1.0f + erff(v1 * 0.70710678118654752f));
                    __nv_bfloat16 h0, l0, h1, l1;
                    split2(v0, h0, l0); split2(v1, h1, l1);
                    *(uint32_t*)(outh + grow * NTOT + gcol) = pack_bf(h0, h1);
                    *(uint32_t*)(outl + grow * NTOT + gcol) = pack_bf(l0, l1);
                } else {
                    *(float2*)(outf + grow * NTOT + gcol) = make_float2(v0, v1);
                }
            }
        }
    }
}

// ================= combine =================
__global__ void combine_kernel(float* __restrict__ out) {
    int n = blockIdx.x;
    int m = g_sortidx[n];
    float scale = g_eprob[m];
    int slot = g_slot[n];
    float4* dst = (float4*)(out + (size_t)n * DIM);
    if (slot < 0) {
        float4 z = make_float4(0.f, 0.f, 0.f, 0.f);
        for (int i = threadIdx.x; i < DIM / 4; i += 256) dst[i] = z;
        return;
    }
    int e = g_eidx[n];
    const float4* src = (const float4*)(g_obuf + (size_t)(e * CAP + slot) * DIM);
    for (int i = threadIdx.x; i < DIM / 4; i += 256) {
        float4 v = src[i];
        dst[i] = make_float4(v.x * scale, v.y * scale, v.z * scale, v.w * scale);
    }
}

// ================= launch =================
extern "C" void kernel_launch(void* const* d_in, const int* in_sizes, int n_in,
                              void* d_out, int out_size) {
    const float* x  = (const float*)d_in[0];
    const float* Wg = (const float*)d_in[1];
    const float* W1 = (const float*)d_in[2];
    const float* b1 = (const float*)d_in[3];
    const float* W2 = (const float*)d_in[4];
    const float* b2 = (const float*)d_in[5];
    float* out = (float*)d_out;
    float* aux_out = (out_size > NTOK * DIM) ? (out + (size_t)NTOK * DIM) : nullptr;

    cudaFuncSetAttribute(gemm_kernel<true, DIM, HID>,
                         cudaFuncAttributeMaxDynamicSharedMemorySize, GEMM_SMEM);
    cudaFuncSetAttribute(gemm_kernel<false, HID, DIM>,
                         cudaFuncAttributeMaxDynamicSharedMemorySize, GEMM_SMEM);

    __nv_bfloat16 *w1h, *w1l, *w2h, *w2l, *xh, *xl, *hh, *hl;
    float* obuf;
    cudaGetSymbolAddress((void**)&w1h, g_w1_hi);
    cudaGetSymbolAddress((void**)&w1l, g_w1_lo);
    cudaGetSymbolAddress((void**)&w2h, g_w2_hi);
    cudaGetSymbolAddress((void**)&w2l, g_w2_lo);
    cudaGetSymbolAddress((void**)&xh, g_x_hi);
    cudaGetSymbolAddress((void**)&xl, g_x_lo);
    cudaGetSymbolAddress((void**)&hh, g_h_hi);
    cudaGetSymbolAddress((void**)&hl, g_h_lo);
    cudaGetSymbolAddress((void**)&obuf, g_obuf);

    init_kernel<<<1, 32>>>();
    router_kernel<<<NTOK, 128>>>(x, Wg);
    reduce_kernel<<<1, 256>>>(aux_out);
    pos_kernel<<<NEXP, 1024>>>();
    gather_kernel<<<NEXP * CAP, 256>>>(x);

    dim3 tb(32, 8);
    transconv_kernel<<<dim3(HID / 32, DIM / 32, NEXP), tb>>>(W1, w1h, w1l, DIM, HID);
    transconv_kernel<<<dim3(DIM / 32, HID / 32, NEXP), tb>>>(W2, w2h, w2l, HID, DIM);

    dim3 g1(HID / 128, CAP / 128, NEXP);
    gemm_kernel<true, DIM, HID><<<g1, 256, GEMM_SMEM>>>(xh, xl, w1h, w1l, b1, hh, hl, nullptr);

    dim3 g2(DIM / 128, CAP / 128, NEXP);
    gemm_kernel<false, HID, DIM><<<g2, 256, GEMM_SMEM>>>(hh, hl, w2h, w2l, b2, nullptr, nullptr, obuf);

    combine_kernel<<<NTOK, 256>>>(out);
}

// round 5
// speedup vs baseline: 2.3249x; 1.0838x over previous
#include <cuda_runtime.h>
#include <cuda_bf16.h>
#include <math.h>
#include <stdint.h>

#define NTOK 8192
#define DIM  1024
#define NEXP 8
#define HID  4096
#define CAP  1024

// ================= scratch =================
__device__ __nv_bfloat16 g_x_hi[(size_t)NTOK * DIM];
__device__ __nv_bfloat16 g_x_lo[(size_t)NTOK * DIM];
__device__ __nv_bfloat16 g_h_hi[(size_t)NTOK * HID];
__device__ __nv_bfloat16 g_h_lo[(size_t)NTOK * HID];
__device__ float         g_obuf[(size_t)NTOK * DIM];
__device__ __nv_bfloat16 g_w1_hi[(size_t)NEXP * HID * DIM];  // [E][H][D]
__device__ __nv_bfloat16 g_w1_lo[(size_t)NEXP * HID * DIM];
__device__ __nv_bfloat16 g_w2_hi[(size_t)NEXP * DIM * HID];  // [E][D][H]
__device__ __nv_bfloat16 g_w2_lo[(size_t)NEXP * DIM * HID];
__device__ float g_probs[(size_t)NTOK * NEXP];
__device__ float g_lse2[NTOK];
__device__ float g_eprob[NTOK];
__device__ int   g_eidx[NTOK];
__device__ int   g_slot[NTOK];
__device__ int   g_sortidx[NTOK];
__device__ int   g_tok_of_slot[NEXP * CAP];
__device__ int   g_counts[NEXP];
__device__ int   g_start[NEXP];

__device__ __forceinline__ void split2(float v, __nv_bfloat16& h, __nv_bfloat16& l) {
    h = __float2bfloat16_rn(v);
    l = __float2bfloat16_rn(v - __bfloat162float(h));
}
__device__ __forceinline__ uint32_t pack_bf(__nv_bfloat16 a, __nv_bfloat16 b) {
    return ((uint32_t)__bfloat16_as_ushort(b) << 16) | (uint32_t)__bfloat16_as_ushort(a);
}
__device__ __forceinline__ uint32_t smem_u32(const void* p) {
    uint32_t a;
    asm("{ .reg .u64 t; cvta.to.shared.u64 t, %1; cvt.u32.u64 %0, t; }" : "=r"(a) : "l"(p));
    return a;
}

// ---- PTX: mma / ldmatrix / cp.async (valid on plain compute_103) ----
__device__ __forceinline__ void mma16816(float* c, const uint32_t* a, const uint32_t* b) {
    asm volatile("mma.sync.aligned.m16n8k16.row.col.f32.bf16.bf16.f32 "
                 "{%0,%1,%2,%3}, {%4,%5,%6,%7}, {%8,%9}, {%0,%1,%2,%3};"
                 : "+f"(c[0]), "+f"(c[1]), "+f"(c[2]), "+f"(c[3])
                 : "r"(a[0]), "r"(a[1]), "r"(a[2]), "r"(a[3]), "r"(b[0]), "r"(b[1]));
}
#define LDSM4(r0, r1, r2, r3, a) \
    asm volatile("ldmatrix.sync.aligned.m8n8.x4.shared.b16 {%0,%1,%2,%3}, [%4];" \
                 : "=r"(r0), "=r"(r1), "=r"(r2), "=r"(r3) : "r"(a))
__device__ __forceinline__ void cp_async16(uint32_t saddr, const void* gptr) {
    asm volatile("cp.async.cg.shared.global [%0], [%1], 16;" :: "r"(saddr), "l"(gptr));
}
#define CP_COMMIT() asm volatile("cp.async.commit_group;" ::: "memory")
#define CP_WAIT2()  asm volatile("cp.async.wait_group 2;" ::: "memory")

// XOR swizzle for 64B rows: bank-conflict-free ldmatrix & cp.async
__device__ __forceinline__ uint32_t swz(uint32_t off) {
    return off ^ (((off >> 7) & 3u) << 4);
}

// ================= init =================
__global__ void init_kernel() {
    if (threadIdx.x < NEXP) g_counts[threadIdx.x] = 0;
}

// ================= router =================
__global__ void router_kernel(const float* __restrict__ x, const float* __restrict__ Wg) {
    int n = blockIdx.x, tid = threadIdx.x;  // 128 threads
    float acc[NEXP];
#pragma unroll
    for (int e = 0; e < NEXP; e++) acc[e] = 0.f;
    const float* xr = x + (size_t)n * DIM;
    for (int d = tid; d < DIM; d += 128) {
        float xv = xr[d];
        const float* w = Wg + (size_t)d * NEXP;
#pragma unroll
        for (int e = 0; e < NEXP; e++) acc[e] += xv * w[e];
    }
    __shared__ float sm[NEXP][128];
#pragma unroll
    for (int e = 0; e < NEXP; e++) sm[e][tid] = acc[e];
    __syncthreads();
    for (int off = 64; off > 0; off >>= 1) {
        if (tid < off)
#pragma unroll
            for (int e = 0; e < NEXP; e++) sm[e][tid] += sm[e][tid + off];
        __syncthreads();
    }
    if (tid == 0) {
        float l[NEXP];
#pragma unroll
        for (int e = 0; e < NEXP; e++) l[e] = sm[e][0];
        float m = l[0]; int bi = 0;
#pragma unroll
        for (int e = 1; e < NEXP; e++) if (l[e] > m) { m = l[e]; bi = e; }
        float p[NEXP], s = 0.f;
#pragma unroll
        for (int e = 0; e < NEXP; e++) { p[e] = expf(l[e] - m); s += p[e]; }
        float inv = 1.f / s;
#pragma unroll
        for (int e = 0; e < NEXP; e++) { p[e] *= inv; g_probs[(size_t)n * NEXP + e] = p[e]; }
        float lse = m + logf(s);
        g_lse2[n] = lse * lse;
        g_eidx[n] = bi;
        g_eprob[n] = p[bi];
        atomicAdd(&g_counts[bi], 1);
    }
}

// ================= reduce =================
__global__ void reduce_kernel(float* aux_out) {
    int tid = threadIdx.x;  // 256
    float z = 0.f, p[NEXP];
#pragma unroll
    for (int e = 0; e < NEXP; e++) p[e] = 0.f;
    for (int n = tid; n < NTOK; n += 256) {
        z += g_lse2[n];
#pragma unroll
        for (int e = 0; e < NEXP; e++) p[e] += g_probs[(size_t)n * NEXP + e];
    }
    __shared__ float sz[256];
    __shared__ float sp[NEXP][256];
    sz[tid] = z;
#pragma unroll
    for (int e = 0; e < NEXP; e++) sp[e][tid] = p[e];
    __syncthreads();
    for (int off = 128; off > 0; off >>= 1) {
        if (tid < off) {
            sz[tid] += sz[tid + off];
#pragma unroll
            for (int e = 0; e < NEXP; e++) sp[e][tid] += sp[e][tid + off];
        }
        __syncthreads();
    }
    if (tid == 0) {
        float zloss = sz[0] / (float)NTOK;
        float dot = 0.f; int run = 0;
#pragma unroll
        for (int e = 0; e < NEXP; e++) {
            float fi = (float)g_counts[e] / (float)NTOK;
            float pi = sp[e][0] / (float)NTOK;
            dot += fi * pi;
            g_start[e] = run;
            run += g_counts[e];
        }
        if (aux_out) *aux_out = 0.01f * (float)NEXP * dot + 0.001f * zloss;
    }
}

// ================= stable per-expert ranks =================
__global__ void pos_kernel() {
    int e = blockIdx.x, tid = threadIdx.x;
    int lane = tid & 31, wid = tid >> 5;
    __shared__ int wsum[32], wbase[32], sbase;
    if (tid == 0) sbase = 0;
    __syncthreads();
    for (int n0 = 0; n0 < NTOK; n0 += 1024) {
        int n = n0 + tid;
        bool pred = (g_eidx[n] == e);
        unsigned b = __ballot_sync(0xffffffffu, pred);
        int wpre = __popc(b & ((1u << lane) - 1u));
        if (lane == 0) wsum[wid] = __popc(b);
        __syncthreads();
        if (tid == 0) {
            int r = sbase;
#pragma unroll
            for (int w = 0; w < 32; w++) { wbase[w] = r; r += wsum[w]; }
            sbase = r;
        }
        __syncthreads();
        if (pred) {
            int pos = wbase[wid] + wpre;
            g_sortidx[g_start[e] + pos] = n;
            if (pos < CAP) { g_slot[n] = pos; g_tok_of_slot[e * CAP + pos] = n; }
            else g_slot[n] = -1;
        }
        __syncthreads();
    }
}

// ================= gather + bf16 split =================
__global__ void gather_kernel(const float* __restrict__ x) {
    int row = blockIdx.x;
    int e = row >> 10;
    int slot = row & (CAP - 1);
    if (slot >= min(g_counts[e], CAP)) return;
    int n = g_tok_of_slot[row];
    const float4* src = (const float4*)(x + (size_t)n * DIM);
    uint2* dh = (uint2*)(g_x_hi + (size_t)row * DIM);
    uint2* dl = (uint2*)(g_x_lo + (size_t)row * DIM);
    for (int i = threadIdx.x; i < DIM / 4; i += 256) {
        float4 v = src[i];
        __nv_bfloat16 h0,l0,h1,l1,h2,l2,h3,l3;
        split2(v.x,h0,l0); split2(v.y,h1,l1); split2(v.z,h2,l2); split2(v.w,h3,l3);
        dh[i] = make_uint2(pack_bf(h0,h1), pack_bf(h2,h3));
        dl[i] = make_uint2(pack_bf(l0,l1), pack_bf(l2,l3));
    }
}

// ================= transpose + bf16 split weights =================
__global__ void transconv_kernel(const float* __restrict__ src,
                                 __nv_bfloat16* __restrict__ dh,
                                 __nv_bfloat16* __restrict__ dl,
                                 int K, int N) {
    __shared__ float t[32][33];
    int e = blockIdx.z;
    const float* s = src + (size_t)e * K * N;
    __nv_bfloat16* oh = dh + (size_t)e * N * K;
    __nv_bfloat16* ol = dl + (size_t)e * N * K;
    int n0 = blockIdx.x * 32, k0 = blockIdx.y * 32;
    int tx = threadIdx.x, ty = threadIdx.y;
#pragma unroll
    for (int i = ty; i < 32; i += 8)
        t[i][tx] = s[(size_t)(k0 + i) * N + n0 + tx];
    __syncthreads();
#pragma unroll
    for (int i = ty; i < 32; i += 8) {
        float v = t[tx][i];
        __nv_bfloat16 h, l; split2(v, h, l);
        size_t o = (size_t)(n0 + i) * K + k0 + tx;
        oh[o] = h; ol[o] = l;
    }
}

// ================= HMMA bf16x3 grouped GEMM: 128x256 tile, 512 thr, 4 stages =================
// Stage (64B rows, XOR swizzled): AH[8192] AL[8192] BH[16384] BL[16384] = 49152 B
#define OFF_AH 0u
#define OFF_AL 8192u
#define OFF_BH 16384u
#define OFF_BL 32768u
#define ST_SZ  49152u
#define NSTAGE 4
#define GEMM_SMEM (NSTAGE * ST_SZ)

template <bool GELU, int K, int NTOT>
__global__ __launch_bounds__(512) void gemm_kernel(
    const __nv_bfloat16* __restrict__ Agh, const __nv_bfloat16* __restrict__ Agl,
    const __nv_bfloat16* __restrict__ Bgh, const __nv_bfloat16* __restrict__ Bgl,
    const float* __restrict__ bias_g,
    __nv_bfloat16* __restrict__ outh, __nv_bfloat16* __restrict__ outl,
    float* __restrict__ outf)
{
    extern __shared__ __align__(128) char smem[];
    const uint32_t sbase = smem_u32(smem);
    const int tid  = threadIdx.x;
    const int wid  = tid >> 5;
    const int lane = tid & 31;
    const int wm   = wid & 3;            // 4 m-warps x 32 rows
    const int wn   = wid >> 2;           // 4 n-warps x 64 cols

    const int e    = blockIdx.z;
    const int row0 = blockIdx.y * 128;   // expert-local row
    const int col0 = blockIdx.x * 256;

    const __nv_bfloat16* Ah = Agh + (size_t)e * CAP * K + (size_t)row0 * K;
    const __nv_bfloat16* Al = Agl + (size_t)e * CAP * K + (size_t)row0 * K;
    const __nv_bfloat16* Bh = Bgh + (size_t)e * NTOT * K + (size_t)col0 * K;
    const __nv_bfloat16* Bl = Bgl + (size_t)e * NTOT * K + (size_t)col0 * K;
    const float* bias = bias_g + (size_t)e * NTOT + col0;
    const size_t orow0 = (size_t)e * CAP + row0;

    float acc[2][8][4];
#pragma unroll
    for (int mt = 0; mt < 2; mt++)
#pragma unroll
        for (int nt = 0; nt < 8; nt++)
#pragma unroll
            for (int q = 0; q < 4; q++) acc[mt][nt][q] = 0.f;

    // ldmatrix per-lane unswizzled offsets + row-derived XOR masks
    const uint32_t aRow  = (uint32_t)(wm * 32 + (lane & 15));
    const uint32_t aBase = aRow * 64 + (uint32_t)((lane >> 4) * 16);
    const uint32_t aMask = ((aRow >> 1) & 3u) << 4;
    const uint32_t bRow  = (uint32_t)(wn * 64 + ((lane >> 4) * 8) + (lane & 7));
    const uint32_t bBase = bRow * 64 + (uint32_t)(((lane >> 3) & 1) * 16);
    const uint32_t bMask = ((bRow >> 1) & 3u) << 4;

    // loader: 3072 x 16B segs per chunk, 6 per thread, uniform per iteration
    const uint32_t lr = (uint32_t)(tid >> 2);      // 0..127
    const uint32_t ls = (uint32_t)(tid & 3);       // 0..3
    const uint32_t storeOff = swz(lr * 64 + ls * 16);
    const uint32_t storeOff2 = swz((lr + 128) * 64 + ls * 16);

    auto prefetch = [&](int c, int stage) {
        const int k0 = c * 32;
        const uint32_t sb = sbase + (uint32_t)stage * ST_SZ;
        const size_t go = (size_t)lr * K + k0 + ls * 8;
        const size_t go2 = (size_t)(lr + 128) * K + k0 + ls * 8;
        cp_async16(sb + OFF_AH + storeOff, Ah + go);
        cp_async16(sb + OFF_AL + storeOff, Al + go);
        cp_async16(sb + OFF_BH + storeOff, Bh + go);
        cp_async16(sb + OFF_BH + storeOff2, Bh + go2);
        cp_async16(sb + OFF_BL + storeOff, Bl + go);
        cp_async16(sb + OFF_BL + storeOff2, Bl + go2);
    };

    const int NC = K / 32;
    prefetch(0, 0); CP_COMMIT();
    prefetch(1, 1); CP_COMMIT();
    prefetch(2, 2); CP_COMMIT();

    for (int c = 0; c < NC; c++) {
        CP_WAIT2();
        __syncthreads();
        if (c + 3 < NC) prefetch(c + 3, (c + 3) & 3);
        CP_COMMIT();

        const uint32_t sb = sbase + (uint32_t)(c & 3) * ST_SZ;
#pragma unroll
        for (int kk = 0; kk < 2; kk++) {
            const uint32_t kByte = (uint32_t)(kk * 32);
            uint32_t ah[2][4], al[2][4];
#pragma unroll
            for (int mt = 0; mt < 2; mt++) {
                uint32_t ua = sb + aBase + (uint32_t)(mt * 1024) + kByte;
                LDSM4(ah[mt][0], ah[mt][1], ah[mt][2], ah[mt][3], (ua + OFF_AH) ^ aMask);
                LDSM4(al[mt][0], al[mt][1], al[mt][2], al[mt][3], (ua + OFF_AL) ^ aMask);
            }
#pragma unroll
            for (int bt = 0; bt < 4; bt++) {
                uint32_t ub = sb + bBase + (uint32_t)(bt * 1024) + kByte;
                uint32_t bh[2][2], bl[2][2];
                uint32_t r0, r1, r2, r3;
                LDSM4(r0, r1, r2, r3, (ub + OFF_BH) ^ bMask);
                bh[0][0] = r0; bh[0][1] = r1; bh[1][0] = r2; bh[1][1] = r3;
                LDSM4(r0, r1, r2, r3, (ub + OFF_BL) ^ bMask);
                bl[0][0] = r0; bl[0][1] = r1; bl[1][0] = r2; bl[1][1] = r3;
#pragma unroll
                for (int mt = 0; mt < 2; mt++)
#pragma unroll
                    for (int j = 0; j < 2; j++)
                        mma16816(acc[mt][2 * bt + j], ah[mt], bh[j]);
#pragma unroll
                for (int mt = 0; mt < 2; mt++)
#pragma unroll
                    for (int j = 0; j < 2; j++)
                        mma16816(acc[mt][2 * bt + j], al[mt], bh[j]);
#pragma unroll
                for (int mt = 0; mt < 2; mt++)
#pragma unroll
                    for (int j = 0; j < 2; j++)
                        mma16816(acc[mt][2 * bt + j], ah[mt], bl[j]);
            }
        }
        __syncthreads();
    }

    // ---- epilogue: bias (+ GELU), store ----
    const int lrow = lane >> 2;
    const int lcol = (lane & 3) * 2;
#pragma unroll
    for (int mt = 0; mt < 2; mt++) {
#pragma unroll
        for (int half = 0; half < 2; half++) {
            size_t grow = orow0 + wm * 32 + mt * 16 + half * 8 + lrow;
#pragma unroll
            for (int nt = 0; nt < 8; nt++) {
                int bc = wn * 64 + nt * 8 + lcol;
                int gcol = col0 + bc;
                float v0 = acc[mt][nt][half * 2 + 0] + bias[bc];
                float v1 = acc[mt][nt][half * 2 + 1] + bias[bc + 1];
                if (GELU) {
                    v0 = 0.5f * v0 * (1.0f + erff(v0 * 0.70710678118654752f));
                    v1 = 0.5f * v1 * (1.0f + erff(v1 * 0.70710678118654752f));
                    __nv_bfloat16 h0, l0, h1, l1;
                    split2(v0, h0, l0); split2(v1, h1, l1);
                    *(uint32_t*)(outh + grow * NTOT + gcol) = pack_bf(h0, h1);
                    *(uint32_t*)(outl + grow * NTOT + gcol) = pack_bf(l0, l1);
                } else {
                    *(float2*)(outf + grow * NTOT + gcol) = make_float2(v0, v1);
                }
            }
        }
    }
}

// ================= combine =================
__global__ void combine_kernel(float* __restrict__ out) {
    int n = blockIdx.x;
    int m = g_sortidx[n];
    float scale = g_eprob[m];
    int slot = g_slot[n];
    float4* dst = (float4*)(out + (size_t)n * DIM);
    if (slot < 0) {
        float4 z = make_float4(0.f, 0.f, 0.f, 0.f);
        for (int i = threadIdx.x; i < DIM / 4; i += 256) dst[i] = z;
        return;
    }
    int e = g_eidx[n];
    const float4* src = (const float4*)(g_obuf + (size_t)(e * CAP + slot) * DIM);
    for (int i = threadIdx.x; i < DIM / 4; i += 256) {
        float4 v = src[i];
        dst[i] = make_float4(v.x * scale, v.y * scale, v.z * scale, v.w * scale);
    }
}

// ================= launch =================
extern "C" void kernel_launch(void* const* d_in, const int* in_sizes, int n_in,
                              void* d_out, int out_size) {
    const float* x  = (const float*)d_in[0];
    const float* Wg = (const float*)d_in[1];
    const float* W1 = (const float*)d_in[2];
    const float* b1 = (const float*)d_in[3];
    const float* W2 = (const float*)d_in[4];
    const float* b2 = (const float*)d_in[5];
    float* out = (float*)d_out;
    float* aux_out = (out_size > NTOK * DIM) ? (out + (size_t)NTOK * DIM) : nullptr;

    cudaFuncSetAttribute(gemm_kernel<true, DIM, HID>,
                         cudaFuncAttributeMaxDynamicSharedMemorySize, GEMM_SMEM);
    cudaFuncSetAttribute(gemm_kernel<false, HID, DIM>,
                         cudaFuncAttributeMaxDynamicSharedMemorySize, GEMM_SMEM);

    __nv_bfloat16 *w1h, *w1l, *w2h, *w2l, *xh, *xl, *hh, *hl;
    float* obuf;
    cudaGetSymbolAddress((void**)&w1h, g_w1_hi);
    cudaGetSymbolAddress((void**)&w1l, g_w1_lo);
    cudaGetSymbolAddress((void**)&w2h, g_w2_hi);
    cudaGetSymbolAddress((void**)&w2l, g_w2_lo);
    cudaGetSymbolAddress((void**)&xh, g_x_hi);
    cudaGetSymbolAddress((void**)&xl, g_x_lo);
    cudaGetSymbolAddress((void**)&hh, g_h_hi);
    cudaGetSymbolAddress((void**)&hl, g_h_lo);
    cudaGetSymbolAddress((void**)&obuf, g_obuf);

    init_kernel<<<1, 32>>>();
    router_kernel<<<NTOK, 128>>>(x, Wg);
    reduce_kernel<<<1, 256>>>(aux_out);
    pos_kernel<<<NEXP, 1024>>>();
    gather_kernel<<<NEXP * CAP, 256>>>(x);

    dim3 tb(32, 8);
    transconv_kernel<<<dim3(HID / 32, DIM / 32, NEXP), tb>>>(W1, w1h, w1l, DIM, HID);
    transconv_kernel<<<dim3(DIM / 32, HID / 32, NEXP), tb>>>(W2, w2h, w2l, HID, DIM);

    dim3 g1(HID / 256, CAP / 128, NEXP);   // 16 x 8 x 8
    gemm_kernel<true, DIM, HID><<<g1, 512, GEMM_SMEM>>>(xh, xl, w1h, w1l, b1, hh, hl, nullptr);

    dim3 g2(DIM / 256, CAP / 128, NEXP);   // 4 x 8 x 8
    gemm_kernel<false, HID, DIM><<<g2, 512, GEMM_SMEM>>>(hh, hl, w2h, w2l, b2, nullptr, nullptr, obuf);

    combine_kernel<<<NTOK, 256>>>(out);
}

// round 6
// speedup vs baseline: 4.8937x; 2.1049x over previous
#include <cuda_runtime.h>
#include <cuda_fp16.h>
#include <math.h>
#include <stdint.h>

#define NTOK 8192
#define DIM  1024
#define NEXP 8
#define HID  4096
#define CAP  1024

// ================= scratch =================
__device__ __half g_xf[(size_t)NTOK * DIM];
__device__ __half g_hf[(size_t)NTOK * HID];
__device__ float  g_obuf[(size_t)NTOK * DIM];
__device__ __half g_w1f[(size_t)NEXP * HID * DIM];  // transposed [E][H][D]
__device__ __half g_w2f[(size_t)NEXP * DIM * HID];  // transposed [E][D][H]
__device__ float g_probs[(size_t)NTOK * NEXP];
__device__ float g_lse2[NTOK];
__device__ float g_eprob[NTOK];
__device__ int   g_eidx[NTOK];
__device__ int   g_slot[NTOK];
__device__ int   g_sortidx[NTOK];
__device__ int   g_tok_of_slot[NEXP * CAP];
__device__ int   g_counts[NEXP];
__device__ int   g_start[NEXP];

__device__ __forceinline__ uint32_t smem_u32(const void* p) {
    uint32_t a;
    asm("{ .reg .u64 t; cvta.to.shared.u64 t, %1; cvt.u32.u64 %0, t; }" : "=r"(a) : "l"(p));
    return a;
}
__device__ __forceinline__ uint32_t pack_h2(float a, float b) {
    __half2 h = __floats2half2_rn(a, b);
    return *(uint32_t*)&h;
}

// ---- PTX: mma / ldmatrix / cp.async (valid on plain compute_103) ----
__device__ __forceinline__ void mma16816(float* c, const uint32_t* a, const uint32_t* b) {
    asm volatile("mma.sync.aligned.m16n8k16.row.col.f32.f16.f16.f32 "
                 "{%0,%1,%2,%3}, {%4,%5,%6,%7}, {%8,%9}, {%0,%1,%2,%3};"
                 : "+f"(c[0]), "+f"(c[1]), "+f"(c[2]), "+f"(c[3])
                 : "r"(a[0]), "r"(a[1]), "r"(a[2]), "r"(a[3]), "r"(b[0]), "r"(b[1]));
}
#define LDSM4(r0, r1, r2, r3, a) \
    asm volatile("ldmatrix.sync.aligned.m8n8.x4.shared.b16 {%0,%1,%2,%3}, [%4];" \
                 : "=r"(r0), "=r"(r1), "=r"(r2), "=r"(r3) : "r"(a))
__device__ __forceinline__ void cp_async16(uint32_t saddr, const void* gptr) {
    asm volatile("cp.async.cg.shared.global [%0], [%1], 16;" :: "r"(saddr), "l"(gptr));
}
#define CP_COMMIT() asm volatile("cp.async.commit_group;" ::: "memory")
#define CP_WAIT2()  asm volatile("cp.async.wait_group 2;" ::: "memory")

// classic SW128 swizzle for 128B rows
__device__ __forceinline__ uint32_t swz(uint32_t off) { return off ^ ((off >> 3) & 0x70); }

// ================= init =================
__global__ void init_kernel() {
    if (threadIdx.x < NEXP) g_counts[threadIdx.x] = 0;
}

// ================= router =================
__global__ void router_kernel(const float* __restrict__ x, const float* __restrict__ Wg) {
    int n = blockIdx.x, tid = threadIdx.x;  // 128 threads
    float acc[NEXP];
#pragma unroll
    for (int e = 0; e < NEXP; e++) acc[e] = 0.f;
    const float* xr = x + (size_t)n * DIM;
    for (int d = tid; d < DIM; d += 128) {
        float xv = xr[d];
        const float* w = Wg + (size_t)d * NEXP;
#pragma unroll
        for (int e = 0; e < NEXP; e++) acc[e] += xv * w[e];
    }
    __shared__ float sm[NEXP][128];
#pragma unroll
    for (int e = 0; e < NEXP; e++) sm[e][tid] = acc[e];
    __syncthreads();
    for (int off = 64; off > 0; off >>= 1) {
        if (tid < off)
#pragma unroll
            for (int e = 0; e < NEXP; e++) sm[e][tid] += sm[e][tid + off];
        __syncthreads();
    }
    if (tid == 0) {
        float l[NEXP];
#pragma unroll
        for (int e = 0; e < NEXP; e++) l[e] = sm[e][0];
        float m = l[0]; int bi = 0;
#pragma unroll
        for (int e = 1; e < NEXP; e++) if (l[e] > m) { m = l[e]; bi = e; }
        float p[NEXP], s = 0.f;
#pragma unroll
        for (int e = 0; e < NEXP; e++) { p[e] = expf(l[e] - m); s += p[e]; }
        float inv = 1.f / s;
#pragma unroll
        for (int e = 0; e < NEXP; e++) { p[e] *= inv; g_probs[(size_t)n * NEXP + e] = p[e]; }
        float lse = m + logf(s);
        g_lse2[n] = lse * lse;
        g_eidx[n] = bi;
        g_eprob[n] = p[bi];
        atomicAdd(&g_counts[bi], 1);
    }
}

// ================= reduce =================
__global__ void reduce_kernel(float* aux_out) {
    int tid = threadIdx.x;  // 256
    float z = 0.f, p[NEXP];
#pragma unroll
    for (int e = 0; e < NEXP; e++) p[e] = 0.f;
    for (int n = tid; n < NTOK; n += 256) {
        z += g_lse2[n];
#pragma unroll
        for (int e = 0; e < NEXP; e++) p[e] += g_probs[(size_t)n * NEXP + e];
    }
    __shared__ float sz[256];
    __shared__ float sp[NEXP][256];
    sz[tid] = z;
#pragma unroll
    for (int e = 0; e < NEXP; e++) sp[e][tid] = p[e];
    __syncthreads();
    for (int off = 128; off > 0; off >>= 1) {
        if (tid < off) {
            sz[tid] += sz[tid + off];
#pragma unroll
            for (int e = 0; e < NEXP; e++) sp[e][tid] += sp[e][tid + off];
        }
        __syncthreads();
    }
    if (tid == 0) {
        float zloss = sz[0] / (float)NTOK;
        float dot = 0.f; int run = 0;
#pragma unroll
        for (int e = 0; e < NEXP; e++) {
            float fi = (float)g_counts[e] / (float)NTOK;
            float pi = sp[e][0] / (float)NTOK;
            dot += fi * pi;
            g_start[e] = run;
            run += g_counts[e];
        }
        if (aux_out) *aux_out = 0.01f * (float)NEXP * dot + 0.001f * zloss;
    }
}

// ================= stable per-expert ranks =================
__global__ void pos_kernel() {
    int e = blockIdx.x, tid = threadIdx.x;
    int lane = tid & 31, wid = tid >> 5;
    __shared__ int wsum[32], wbase[32], sbase;
    if (tid == 0) sbase = 0;
    __syncthreads();
    for (int n0 = 0; n0 < NTOK; n0 += 1024) {
        int n = n0 + tid;
        bool pred = (g_eidx[n] == e);
        unsigned b = __ballot_sync(0xffffffffu, pred);
        int wpre = __popc(b & ((1u << lane) - 1u));
        if (lane == 0) wsum[wid] = __popc(b);
        __syncthreads();
        if (tid == 0) {
            int r = sbase;
#pragma unroll
            for (int w = 0; w < 32; w++) { wbase[w] = r; r += wsum[w]; }
            sbase = r;
        }
        __syncthreads();
        if (pred) {
            int pos = wbase[wid] + wpre;
            g_sortidx[g_start[e] + pos] = n;
            if (pos < CAP) { g_slot[n] = pos; g_tok_of_slot[e * CAP + pos] = n; }
            else g_slot[n] = -1;
        }
        __syncthreads();
    }
}

// ================= gather -> fp16 =================
__global__ void gather_kernel(const float* __restrict__ x) {
    int row = blockIdx.x;
    int e = row >> 10;
    int slot = row & (CAP - 1);
    if (slot >= min(g_counts[e], CAP)) return;
    int n = g_tok_of_slot[row];
    const float4* src = (const float4*)(x + (size_t)n * DIM);
    uint2* dst = (uint2*)(g_xf + (size_t)row * DIM);
    for (int i = threadIdx.x; i < DIM / 4; i += 256) {
        float4 v = src[i];
        dst[i] = make_uint2(pack_h2(v.x, v.y), pack_h2(v.z, v.w));
    }
}

// ================= transpose + fp16 convert weights =================
// src [E][K][N] fp32 -> dst [E][N][K] fp16
__global__ void transconv_kernel(const float* __restrict__ src,
                                 __half* __restrict__ dst, int K, int N) {
    __shared__ float t[32][33];
    int e = blockIdx.z;
    const float* s = src + (size_t)e * K * N;
    __half* o = dst + (size_t)e * N * K;
    int n0 = blockIdx.x * 32, k0 = blockIdx.y * 32;
    int tx = threadIdx.x, ty = threadIdx.y;  // 32 x 8
#pragma unroll
    for (int i = ty; i < 32; i += 8)
        t[i][tx] = s[(size_t)(k0 + i) * N + n0 + tx];
    __syncthreads();
#pragma unroll
    for (int i = ty; i < 32; i += 8)
        o[(size_t)(n0 + i) * K + k0 + tx] = __float2half_rn(t[tx][i]);
}

// ================= fp16 HMMA grouped GEMM: 128x256 tile, 512 thr, BK=64, 4 stages =================
// Stage (128B rows, SW128): A[128x128B=16K] B[256x128B=32K] = 48K; x4 = 192KB
#define OFF_A  0u
#define OFF_B  16384u
#define ST_SZ  49152u
#define GEMM_SMEM (4u * ST_SZ)

template <bool GELU, int K, int NTOT>
__global__ __launch_bounds__(512) void gemm_kernel(
    const __half* __restrict__ Ag, const __half* __restrict__ Bg,
    const float* __restrict__ bias_g,
    __half* __restrict__ outh, float* __restrict__ outf)
{
    extern __shared__ __align__(128) char smem[];
    const uint32_t sbase = smem_u32(smem);
    const int tid  = threadIdx.x;
    const int wid  = tid >> 5;
    const int lane = tid & 31;
    const int wm   = wid & 3;            // 4 m-warps x 32 rows
    const int wn   = wid >> 2;           // 4 n-warps x 64 cols

    const int e    = blockIdx.z;
    const int row0 = blockIdx.y * 128;
    const int col0 = blockIdx.x * 256;

    const __half* A = Ag + (size_t)e * CAP * K + (size_t)row0 * K;
    const __half* B = Bg + (size_t)e * NTOT * K + (size_t)col0 * K;
    const float* bias = bias_g + (size_t)e * NTOT + col0;
    const size_t orow0 = (size_t)e * CAP + row0;

    float acc[2][8][4];
#pragma unroll
    for (int mt = 0; mt < 2; mt++)
#pragma unroll
        for (int nt = 0; nt < 8; nt++)
#pragma unroll
            for (int q = 0; q < 4; q++) acc[mt][nt][q] = 0.f;

    // ldmatrix per-lane offsets (row-derived XOR masks, SW128)
    const uint32_t aRow  = (uint32_t)(wm * 32 + (lane & 15));
    const uint32_t aBase = aRow * 128 + (uint32_t)((lane >> 4) * 16);
    const uint32_t aMask = (aRow & 7u) << 4;
    const uint32_t bRow  = (uint32_t)(wn * 64 + ((lane >> 4) * 8) + (lane & 7));
    const uint32_t bBase = bRow * 128 + (uint32_t)(((lane >> 3) & 1) * 16);
    const uint32_t bMask = (bRow & 7u) << 4;

    // loader: 3072 x 16B segs per chunk = 6 per thread (2 A rows + 4 B rows)
    const uint32_t lr = (uint32_t)(tid >> 3);      // 0..63
    const uint32_t ls = (uint32_t)(tid & 7);       // 0..7
    const uint32_t sA0 = OFF_A + swz((lr +   0) * 128 + ls * 16);
    const uint32_t sA1 = OFF_A + swz((lr +  64) * 128 + ls * 16);
    const uint32_t sB0 = OFF_B + swz((lr +   0) * 128 + ls * 16);
    const uint32_t sB1 = OFF_B + swz((lr +  64) * 128 + ls * 16);
    const uint32_t sB2 = OFF_B + swz((lr + 128) * 128 + ls * 16);
    const uint32_t sB3 = OFF_B + swz((lr + 192) * 128 + ls * 16);
    const __half* gA0 = A + (size_t)(lr +   0) * K + ls * 8;
    const __half* gA1 = A + (size_t)(lr +  64) * K + ls * 8;
    const __half* gB0 = B + (size_t)(lr +   0) * K + ls * 8;
    const __half* gB1 = B + (size_t)(lr +  64) * K + ls * 8;
    const __half* gB2 = B + (size_t)(lr + 128) * K + ls * 8;
    const __half* gB3 = B + (size_t)(lr + 192) * K + ls * 8;

    auto prefetch = [&](int c, int stage) {
        const uint32_t sb = sbase + (uint32_t)stage * ST_SZ;
        const size_t ko = (size_t)c * 64;
        cp_async16(sb + sA0, gA0 + ko);
        cp_async16(sb + sA1, gA1 + ko);
        cp_async16(sb + sB0, gB0 + ko);
        cp_async16(sb + sB1, gB1 + ko);
        cp_async16(sb + sB2, gB2 + ko);
        cp_async16(sb + sB3, gB3 + ko);
    };

    const int NC = K / 64;
    prefetch(0, 0); CP_COMMIT();
    prefetch(1, 1); CP_COMMIT();
    prefetch(2, 2); CP_COMMIT();
    CP_WAIT2();
    __syncthreads();

    for (int c = 0; c < NC; c++) {
        // stage c is visible; writing stage (c+3)&3 == (c-1)&3 is safe (sync'ed)
        if (c + 3 < NC) prefetch(c + 3, (c + 3) & 3);
        CP_COMMIT();

        const uint32_t sb = sbase + (uint32_t)(c & 3) * ST_SZ;
#pragma unroll
        for (int kk = 0; kk < 4; kk++) {
            const uint32_t kByte = (uint32_t)(kk * 32);
            uint32_t af[2][4];
#pragma unroll
            for (int mt = 0; mt < 2; mt++) {
                uint32_t ua = (sb + OFF_A + aBase + (uint32_t)(mt * 2048) + kByte) ^ aMask;
                LDSM4(af[mt][0], af[mt][1], af[mt][2], af[mt][3], ua);
            }
#pragma unroll
            for (int bt = 0; bt < 4; bt++) {
                uint32_t ub = (sb + OFF_B + bBase + (uint32_t)(bt * 2048) + kByte) ^ bMask;
                uint32_t r0, r1, r2, r3;
                LDSM4(r0, r1, r2, r3, ub);
                uint32_t bf0[2] = {r0, r1}, bf1[2] = {r2, r3};
#pragma unroll
                for (int mt = 0; mt < 2; mt++) {
                    mma16816(acc[mt][2 * bt + 0], af[mt], bf0);
                    mma16816(acc[mt][2 * bt + 1], af[mt], bf1);
                }
            }
        }
        CP_WAIT2();
        __syncthreads();
    }

    // ---- epilogue: bias (+ GELU), store ----
    const int lrow = lane >> 2;
    const int lcol = (lane & 3) * 2;
#pragma unroll
    for (int mt = 0; mt < 2; mt++) {
#pragma unroll
        for (int half = 0; half < 2; half++) {
            size_t grow = orow0 + wm * 32 + mt * 16 + half * 8 + lrow;
#pragma unroll
            for (int nt = 0; nt < 8; nt++) {
                int bc = wn * 64 + nt * 8 + lcol;
                int gcol = col0 + bc;
                float v0 = acc[mt][nt][half * 2 + 0] + bias[bc];
                float v1 = acc[mt][nt][half * 2 + 1] + bias[bc + 1];
                if (GELU) {
                    v0 = 0.5f * v0 * (1.0f + erff(v0 * 0.70710678118654752f));
                    v1 = 0.5f * v1 * (1.0f + erff(v1 * 0.70710678118654752f));
                    *(uint32_t*)(outh + grow * NTOT + gcol) = pack_h2(v0, v1);
                } else {
                    *(float2*)(outf + grow * NTOT + gcol) = make_float2(v0, v1);
                }
            }
        }
    }
}

// ================= combine =================
__global__ void combine_kernel(float* __restrict__ out) {
    int n = blockIdx.x;
    int m = g_sortidx[n];
    float scale = g_eprob[m];
    int slot = g_slot[n];
    float4* dst = (float4*)(out + (size_t)n * DIM);
    if (slot < 0) {
        float4 z = make_float4(0.f, 0.f, 0.f, 0.f);
        for (int i = threadIdx.x; i < DIM / 4; i += 256) dst[i] = z;
        return;
    }
    int e = g_eidx[n];
    const float4* src = (const float4*)(g_obuf + (size_t)(e * CAP + slot) * DIM);
    for (int i = threadIdx.x; i < DIM / 4; i += 256) {
        float4 v = src[i];
        dst[i] = make_float4(v.x * scale, v.y * scale, v.z * scale, v.w * scale);
    }
}

// ================= launch =================
extern "C" void kernel_launch(void* const* d_in, const int* in_sizes, int n_in,
                              void* d_out, int out_size) {
    const float* x  = (const float*)d_in[0];
    const float* Wg = (const float*)d_in[1];
    const float* W1 = (const float*)d_in[2];
    const float* b1 = (const float*)d_in[3];
    const float* W2 = (const float*)d_in[4];
    const float* b2 = (const float*)d_in[5];
    float* out = (float*)d_out;
    float* aux_out = (out_size > NTOK * DIM) ? (out + (size_t)NTOK * DIM) : nullptr;

    cudaFuncSetAttribute(gemm_kernel<true, DIM, HID>,
                         cudaFuncAttributeMaxDynamicSharedMemorySize, GEMM_SMEM);
    cudaFuncSetAttribute(gemm_kernel<false, HID, DIM>,
                         cudaFuncAttributeMaxDynamicSharedMemorySize, GEMM_SMEM);

    __half *w1f, *w2f, *xf, *hf;
    float* obuf;
    cudaGetSymbolAddress((void**)&w1f, g_w1f);
    cudaGetSymbolAddress((void**)&w2f, g_w2f);
    cudaGetSymbolAddress((void**)&xf, g_xf);
    cudaGetSymbolAddress((void**)&hf, g_hf);
    cudaGetSymbolAddress((void**)&obuf, g_obuf);

    init_kernel<<<1, 32>>>();
    router_kernel<<<NTOK, 128>>>(x, Wg);
    reduce_kernel<<<1, 256>>>(aux_out);
    pos_kernel<<<NEXP, 1024>>>();
    gather_kernel<<<NEXP * CAP, 256>>>(x);

    dim3 tb(32, 8);
    transconv_kernel<<<dim3(HID / 32, DIM / 32, NEXP), tb>>>(W1, w1f, DIM, HID);
    transconv_kernel<<<dim3(DIM / 32, HID / 32, NEXP), tb>>>(W2, w2f, HID, DIM);

    dim3 g1(HID / 256, CAP / 128, NEXP);   // 16 x 8 x 8
    gemm_kernel<true, DIM, HID><<<g1, 512, GEMM_SMEM>>>(xf, w1f, b1, hf, nullptr);

    dim3 g2(DIM / 256, CAP / 128, NEXP);   // 4 x 8 x 8
    gemm_kernel<false, HID, DIM><<<g2, 512, GEMM_SMEM>>>(hf, w2f, b2, nullptr, obuf);

    combine_kernel<<<NTOK, 256>>>(out);
}

// round 7
// speedup vs baseline: 5.6795x; 1.1606x over previous
#include <cuda_runtime.h>
#include <cuda_fp16.h>
#include <math.h>
#include <stdint.h>

#define NTOK 8192
#define DIM  1024
#define NEXP 8
#define HID  4096
#define CAP  1024

// ================= scratch =================
__device__ __half g_xf[(size_t)NTOK * DIM];
__device__ __half g_hf[(size_t)NTOK * HID];
__device__ __half g_w1f[(size_t)NEXP * HID * DIM];  // transposed [E][H][D]
__device__ __half g_w2f[(size_t)NEXP * DIM * HID];  // transposed [E][D][H]
__device__ float g_probs[(size_t)NTOK * NEXP];
__device__ float g_lse2[NTOK];
__device__ float g_eprob[NTOK];
__device__ float g_oscale[NTOK];
__device__ int   g_eidx[NTOK];
__device__ int   g_slot[NTOK];
__device__ int   g_sortidx[NTOK];
__device__ int   g_tok_of_slot[NEXP * CAP];
__device__ int   g_counts[NEXP];
__device__ int   g_start[NEXP];

__device__ __forceinline__ uint32_t smem_u32(const void* p) {
    uint32_t a;
    asm("{ .reg .u64 t; cvta.to.shared.u64 t, %1; cvt.u32.u64 %0, t; }" : "=r"(a) : "l"(p));
    return a;
}
__device__ __forceinline__ uint32_t pack_h2(float a, float b) {
    __half2 h = __floats2half2_rn(a, b);
    return *(uint32_t*)&h;
}

// ---- PTX: mma / ldmatrix / cp.async (valid on plain compute_103) ----
__device__ __forceinline__ void mma16816(float* c, const uint32_t* a, const uint32_t* b) {
    asm volatile("mma.sync.aligned.m16n8k16.row.col.f32.f16.f16.f32 "
                 "{%0,%1,%2,%3}, {%4,%5,%6,%7}, {%8,%9}, {%0,%1,%2,%3};"
                 : "+f"(c[0]), "+f"(c[1]), "+f"(c[2]), "+f"(c[3])
                 : "r"(a[0]), "r"(a[1]), "r"(a[2]), "r"(a[3]), "r"(b[0]), "r"(b[1]));
}
#define LDSM4(r0, r1, r2, r3, a) \
    asm volatile("ldmatrix.sync.aligned.m8n8.x4.shared.b16 {%0,%1,%2,%3}, [%4];" \
                 : "=r"(r0), "=r"(r1), "=r"(r2), "=r"(r3) : "r"(a))
__device__ __forceinline__ void cp_async16(uint32_t saddr, const void* gptr) {
    asm volatile("cp.async.cg.shared.global [%0], [%1], 16;" :: "r"(saddr), "l"(gptr));
}
#define CP_COMMIT() asm volatile("cp.async.commit_group;" ::: "memory")
#define CP_WAIT1()  asm volatile("cp.async.wait_group 1;" ::: "memory")

// classic SW128 swizzle for 128B rows
__device__ __forceinline__ uint32_t swz(uint32_t off) { return off ^ ((off >> 3) & 0x70); }

// ================= init =================
__global__ void init_kernel() {
    if (threadIdx.x < NEXP) g_counts[threadIdx.x] = 0;
}

// ================= router =================
__global__ void router_kernel(const float* __restrict__ x, const float* __restrict__ Wg) {
    int n = blockIdx.x, tid = threadIdx.x;  // 128 threads
    float acc[NEXP];
#pragma unroll
    for (int e = 0; e < NEXP; e++) acc[e] = 0.f;
    const float* xr = x + (size_t)n * DIM;
    for (int d = tid; d < DIM; d += 128) {
        float xv = xr[d];
        const float* w = Wg + (size_t)d * NEXP;
#pragma unroll
        for (int e = 0; e < NEXP; e++) acc[e] += xv * w[e];
    }
    __shared__ float sm[NEXP][128];
#pragma unroll
    for (int e = 0; e < NEXP; e++) sm[e][tid] = acc[e];
    __syncthreads();
    for (int off = 64; off > 0; off >>= 1) {
        if (tid < off)
#pragma unroll
            for (int e = 0; e < NEXP; e++) sm[e][tid] += sm[e][tid + off];
        __syncthreads();
    }
    if (tid == 0) {
        float l[NEXP];
#pragma unroll
        for (int e = 0; e < NEXP; e++) l[e] = sm[e][0];
        float m = l[0]; int bi = 0;
#pragma unroll
        for (int e = 1; e < NEXP; e++) if (l[e] > m) { m = l[e]; bi = e; }
        float p[NEXP], s = 0.f;
#pragma unroll
        for (int e = 0; e < NEXP; e++) { p[e] = expf(l[e] - m); s += p[e]; }
        float inv = 1.f / s;
#pragma unroll
        for (int e = 0; e < NEXP; e++) { p[e] *= inv; g_probs[(size_t)n * NEXP + e] = p[e]; }
        float lse = m + logf(s);
        g_lse2[n] = lse * lse;
        g_eidx[n] = bi;
        g_eprob[n] = p[bi];
        atomicAdd(&g_counts[bi], 1);
    }
}

// ================= reduce =================
__global__ void reduce_kernel(float* aux_out) {
    int tid = threadIdx.x;  // 256
    float z = 0.f, p[NEXP];
#pragma unroll
    for (int e = 0; e < NEXP; e++) p[e] = 0.f;
    for (int n = tid; n < NTOK; n += 256) {
        z += g_lse2[n];
#pragma unroll
        for (int e = 0; e < NEXP; e++) p[e] += g_probs[(size_t)n * NEXP + e];
    }
    __shared__ float sz[256];
    __shared__ float sp[NEXP][256];
    sz[tid] = z;
#pragma unroll
    for (int e = 0; e < NEXP; e++) sp[e][tid] = p[e];
    __syncthreads();
    for (int off = 128; off > 0; off >>= 1) {
        if (tid < off) {
            sz[tid] += sz[tid + off];
#pragma unroll
            for (int e = 0; e < NEXP; e++) sp[e][tid] += sp[e][tid + off];
        }
        __syncthreads();
    }
    if (tid == 0) {
        float zloss = sz[0] / (float)NTOK;
        float dot = 0.f; int run = 0;
#pragma unroll
        for (int e = 0; e < NEXP; e++) {
            float fi = (float)g_counts[e] / (float)NTOK;
            float pi = sp[e][0] / (float)NTOK;
            dot += fi * pi;
            g_start[e] = run;
            run += g_counts[e];
        }
        if (aux_out) *aux_out = 0.01f * (float)NEXP * dot + 0.001f * zloss;
    }
}

// ================= stable per-expert ranks =================
__global__ void pos_kernel() {
    int e = blockIdx.x, tid = threadIdx.x;
    int lane = tid & 31, wid = tid >> 5;
    __shared__ int wsum[32], wbase[32], sbase;
    if (tid == 0) sbase = 0;
    __syncthreads();
    for (int n0 = 0; n0 < NTOK; n0 += 1024) {
        int n = n0 + tid;
        bool pred = (g_eidx[n] == e);
        unsigned b = __ballot_sync(0xffffffffu, pred);
        int wpre = __popc(b & ((1u << lane) - 1u));
        if (lane == 0) wsum[wid] = __popc(b);
        __syncthreads();
        if (tid == 0) {
            int r = sbase;
#pragma unroll
            for (int w = 0; w < 32; w++) { wbase[w] = r; r += wsum[w]; }
            sbase = r;
        }
        __syncthreads();
        if (pred) {
            int pos = wbase[wid] + wpre;
            g_sortidx[g_start[e] + pos] = n;
            if (pos < CAP) { g_slot[n] = pos; g_tok_of_slot[e * CAP + pos] = n; }
            else g_slot[n] = -1;
        }
        __syncthreads();
    }
}

// ================= output scale: oscale[n] = eprob[sortidx[n]] =================
__global__ void oscale_kernel() {
    int n = blockIdx.x * 256 + threadIdx.x;
    g_oscale[n] = g_eprob[g_sortidx[n]];
}

// ================= gather -> fp16 =================
__global__ void gather_kernel(const float* __restrict__ x) {
    int row = blockIdx.x;
    int e = row >> 10;
    int slot = row & (CAP - 1);
    if (slot >= min(g_counts[e], CAP)) return;
    int n = g_tok_of_slot[row];
    const float4* src = (const float4*)(x + (size_t)n * DIM);
    uint2* dst = (uint2*)(g_xf + (size_t)row * DIM);
    for (int i = threadIdx.x; i < DIM / 4; i += 256) {
        float4 v = src[i];
        dst[i] = make_uint2(pack_h2(v.x, v.y), pack_h2(v.z, v.w));
    }
}

// ================= transpose + fp16 convert weights (64x64 tiles) =================
// src [E][K][N] fp32 -> dst [E][N][K] fp16
__global__ __launch_bounds__(256) void transconv_kernel(const float* __restrict__ src,
                                                        __half* __restrict__ dst,
                                                        int K, int N) {
    __shared__ float t[64][65];
    int e = blockIdx.z;
    const float* s = src + (size_t)e * K * N;
    __half* o = dst + (size_t)e * N * K;
    int n0 = blockIdx.x * 64, k0 = blockIdx.y * 64;
    int tid = threadIdx.x;
    // load 64x64 floats, coalesced
#pragma unroll
    for (int i = 0; i < 16; i++) {
        int lin = i * 256 + tid;
        int kr = lin >> 6, nc = lin & 63;
        t[kr][nc] = s[(size_t)(k0 + kr) * N + n0 + nc];
    }
    __syncthreads();
    // store: thread (r = tid>>2, c4 = tid&3) writes 16 halves of row n0+r at k0+c4*16
    int r = tid >> 2, c4 = tid & 3;
    uint32_t w[8];
#pragma unroll
    for (int j = 0; j < 8; j++) {
        float a = t[c4 * 16 + 2 * j][r];
        float b = t[c4 * 16 + 2 * j + 1][r];
        w[j] = pack_h2(a, b);
    }
    uint4* dp = (uint4*)(o + (size_t)(n0 + r) * K + k0 + c4 * 16);
    dp[0] = make_uint4(w[0], w[1], w[2], w[3]);
    dp[1] = make_uint4(w[4], w[5], w[6], w[7]);
}

// ================= fp16 HMMA grouped GEMM: 128x128 tile, 256 thr, BK=64, 3 stages =================
#define OFF_A  0u
#define OFF_B  16384u
#define ST_SZ  32768u
#define GEMM_SMEM (3u * ST_SZ)

// MODE 0: GELU epilogue -> fp16 hidden (rows e*CAP + local)
// MODE 1: final epilogue -> out[token] * oscale, predicated on slot<count
template <int MODE, int K, int NTOT>
__global__ __launch_bounds__(256, 2) void gemm_kernel(
    const __half* __restrict__ Ag, const __half* __restrict__ Bg,
    const float* __restrict__ bias_g,
    __half* __restrict__ outh, float* __restrict__ outf)
{
    extern __shared__ __align__(128) char smem[];
    const uint32_t sbase = smem_u32(smem);
    const int tid  = threadIdx.x;
    const int wid  = tid >> 5;
    const int lane = tid & 31;
    const int wm   = wid & 3;            // 4 m-warps x 32 rows
    const int wn   = wid >> 2;           // 2 n-warps x 64 cols

    const int e    = blockIdx.z;
    const int row0 = blockIdx.y * 128;
    const int col0 = blockIdx.x * 128;

    const __half* A = Ag + (size_t)e * CAP * K + (size_t)row0 * K;
    const __half* B = Bg + (size_t)e * NTOT * K + (size_t)col0 * K;
    const float* bias = bias_g + (size_t)e * NTOT + col0;

    float acc[2][8][4];
#pragma unroll
    for (int mt = 0; mt < 2; mt++)
#pragma unroll
        for (int nt = 0; nt < 8; nt++)
#pragma unroll
            for (int q = 0; q < 4; q++) acc[mt][nt][q] = 0.f;

    // ldmatrix per-lane offsets (SW128, row-XOR form)
    const uint32_t aRow  = (uint32_t)(wm * 32 + (lane & 15));
    const uint32_t aBase = aRow * 128 + (uint32_t)((lane >> 4) * 16);
    const uint32_t aMask = (aRow & 7u) << 4;
    const uint32_t bRow  = (uint32_t)(wn * 64 + ((lane >> 4) * 8) + (lane & 7));
    const uint32_t bBase = bRow * 128 + (uint32_t)(((lane >> 3) & 1) * 16);
    const uint32_t bMask = (bRow & 7u) << 4;

    // loader: 2048 x 16B segs per chunk = 8 per thread (4 A rows + 4 B rows)
    const uint32_t lr = (uint32_t)(tid >> 3);      // 0..31
    const uint32_t ls = (uint32_t)(tid & 7);       // 0..7
    uint32_t sOffA[4], sOffB[4];
    const __half *gA[4], *gB[4];
#pragma unroll
    for (int q = 0; q < 4; q++) {
        uint32_t r = lr + q * 32;
        sOffA[q] = OFF_A + swz(r * 128 + ls * 16);
        sOffB[q] = OFF_B + swz(r * 128 + ls * 16);
        gA[q] = A + (size_t)r * K + ls * 8;
        gB[q] = B + (size_t)r * K + ls * 8;
    }

    auto prefetch = [&](int c, int stage) {
        const uint32_t sb = sbase + (uint32_t)stage * ST_SZ;
        const size_t ko = (size_t)c * 64;
#pragma unroll
        for (int q = 0; q < 4; q++) {
            cp_async16(sb + sOffA[q], gA[q] + ko);
            cp_async16(sb + sOffB[q], gB[q] + ko);
        }
    };

    const int NC = K / 64;
    prefetch(0, 0); CP_COMMIT();
    prefetch(1, 1); CP_COMMIT();

    int stage = 0;
    for (int c = 0; c < NC; c++) {
        CP_WAIT1();
        __syncthreads();
        if (c + 2 < NC) prefetch(c + 2, (stage + 2) % 3);
        CP_COMMIT();

        const uint32_t sb = sbase + (uint32_t)stage * ST_SZ;
#pragma unroll
        for (int kk = 0; kk < 4; kk++) {
            const uint32_t kByte = (uint32_t)(kk * 32);
            uint32_t af[2][4];
#pragma unroll
            for (int mt = 0; mt < 2; mt++) {
                uint32_t ua = (sb + OFF_A + aBase + (uint32_t)(mt * 2048) + kByte) ^ aMask;
                LDSM4(af[mt][0], af[mt][1], af[mt][2], af[mt][3], ua);
            }
#pragma unroll
            for (int bt = 0; bt < 4; bt++) {
                uint32_t ub = (sb + OFF_B + bBase + (uint32_t)(bt * 2048) + kByte) ^ bMask;
                uint32_t r0, r1, r2, r3;
                LDSM4(r0, r1, r2, r3, ub);
                uint32_t bf0[2] = {r0, r1}, bf1[2] = {r2, r3};
#pragma unroll
                for (int mt = 0; mt < 2; mt++) {
                    mma16816(acc[mt][2 * bt + 0], af[mt], bf0);
                    mma16816(acc[mt][2 * bt + 1], af[mt], bf1);
                }
            }
        }
        stage = (stage + 1) % 3;
    }

    // ---- epilogue ----
    const int lrow = lane >> 2;
    const int lcol = (lane & 3) * 2;
    if (MODE == 0) {
        const size_t orow0 = (size_t)e * CAP + row0;
#pragma unroll
        for (int mt = 0; mt < 2; mt++)
#pragma unroll
            for (int half = 0; half < 2; half++) {
                size_t grow = orow0 + wm * 32 + mt * 16 + half * 8 + lrow;
#pragma unroll
                for (int nt = 0; nt < 8; nt++) {
                    int bc = wn * 64 + nt * 8 + lcol;
                    float v0 = acc[mt][nt][half * 2 + 0] + bias[bc];
                    float v1 = acc[mt][nt][half * 2 + 1] + bias[bc + 1];
                    v0 = 0.5f * v0 * (1.0f + erff(v0 * 0.70710678118654752f));
                    v1 = 0.5f * v1 * (1.0f + erff(v1 * 0.70710678118654752f));
                    *(uint32_t*)(outh + grow * NTOT + col0 + bc) = pack_h2(v0, v1);
                }
            }
    } else {
        const int count = min(g_counts[e], CAP);
#pragma unroll
        for (int mt = 0; mt < 2; mt++)
#pragma unroll
            for (int half = 0; half < 2; half++) {
                int lrw = row0 + wm * 32 + mt * 16 + half * 8 + lrow;
                if (lrw < count) {
                    int n = g_tok_of_slot[e * CAP + lrw];
                    float scale = g_oscale[n];
                    float* orow = outf + (size_t)n * NTOT;
#pragma unroll
                    for (int nt = 0; nt < 8; nt++) {
                        int bc = wn * 64 + nt * 8 + lcol;
                        float v0 = (acc[mt][nt][half * 2 + 0] + bias[bc]) * scale;
                        float v1 = (acc[mt][nt][half * 2 + 1] + bias[bc + 1]) * scale;
                        *(float2*)(orow + col0 + bc) = make_float2(v0, v1);
                    }
                }
            }
    }
}

// ================= launch =================
extern "C" void kernel_launch(void* const* d_in, const int* in_sizes, int n_in,
                              void* d_out, int out_size) {
    const float* x  = (const float*)d_in[0];
    const float* Wg = (const float*)d_in[1];
    const float* W1 = (const float*)d_in[2];
    const float* b1 = (const float*)d_in[3];
    const float* W2 = (const float*)d_in[4];
    const float* b2 = (const float*)d_in[5];
    float* out = (float*)d_out;
    float* aux_out = (out_size > NTOK * DIM) ? (out + (size_t)NTOK * DIM) : nullptr;

    cudaFuncSetAttribute(gemm_kernel<0, DIM, HID>,
                         cudaFuncAttributeMaxDynamicSharedMemorySize, GEMM_SMEM);
    cudaFuncSetAttribute(gemm_kernel<1, HID, DIM>,
                         cudaFuncAttributeMaxDynamicSharedMemorySize, GEMM_SMEM);

    __half *w1f, *w2f, *xf, *hf;
    cudaGetSymbolAddress((void**)&w1f, g_w1f);
    cudaGetSymbolAddress((void**)&w2f, g_w2f);
    cudaGetSymbolAddress((void**)&xf, g_xf);
    cudaGetSymbolAddress((void**)&hf, g_hf);

    cudaMemsetAsync(out, 0, (size_t)out_size * sizeof(float), 0);

    init_kernel<<<1, 32>>>();
    router_kernel<<<NTOK, 128>>>(x, Wg);
    reduce_kernel<<<1, 256>>>(aux_out);
    pos_kernel<<<NEXP, 1024>>>();
    oscale_kernel<<<NTOK / 256, 256>>>();
    gather_kernel<<<NEXP * CAP, 256>>>(x);

    transconv_kernel<<<dim3(HID / 64, DIM / 64, NEXP), 256>>>(W1, w1f, DIM, HID);
    transconv_kernel<<<dim3(DIM / 64, HID / 64, NEXP), 256>>>(W2, w2f, HID, DIM);

    dim3 g1(HID / 128, CAP / 128, NEXP);   // 32 x 8 x 8
    gemm_kernel<0, DIM, HID><<<g1, 256, GEMM_SMEM>>>(xf, w1f, b1, hf, nullptr);

    dim3 g2(DIM / 128, CAP / 128, NEXP);   // 8 x 8 x 8
    gemm_kernel<1, HID, DIM><<<g2, 256, GEMM_SMEM>>>(hf, w2f, b2, nullptr, out);
}

// round 11
// speedup vs baseline: 6.3869x; 1.1245x over previous
#include <cuda_runtime.h>
#include <cuda_fp16.h>
#include <math.h>
#include <stdint.h>

#define NTOK 8192
#define DIM  1024
#define NEXP 8
#define HID  4096
#define CAP  1024

// ================= scratch =================
__device__ __half g_xf[(size_t)NTOK * DIM];
__device__ __half g_hf[(size_t)NTOK * HID];
__device__ __half g_w1f[(size_t)NEXP * HID * DIM];  // transposed [E][H][D]
__device__ __half g_w2f[(size_t)NEXP * DIM * HID];  // transposed [E][D][H]
__device__ float g_probs[(size_t)NTOK * NEXP];
__device__ float g_lse2[NTOK];
__device__ float g_eprob[NTOK];
__device__ float g_oscale[NTOK];
__device__ int   g_eidx[NTOK];
__device__ int   g_slot[NTOK];
__device__ int   g_sortidx[NTOK];
__device__ int   g_tok_of_slot[NEXP * CAP];
__device__ int   g_counts[NEXP];

__device__ __forceinline__ uint32_t smem_u32(const void* p) {
    uint32_t a;
    asm("{ .reg .u64 t; cvta.to.shared.u64 t, %1; cvt.u32.u64 %0, t; }" : "=r"(a) : "l"(p));
    return a;
}
__device__ __forceinline__ uint32_t pack_h2(float a, float b) {
    __half2 h = __floats2half2_rn(a, b);
    return *(uint32_t*)&h;
}

// ---- PTX: mma / ldmatrix / cp.async ----
__device__ __forceinline__ void mma16816(float* c, const uint32_t* a, const uint32_t* b) {
    asm volatile("mma.sync.aligned.m16n8k16.row.col.f32.f16.f16.f32 "
                 "{%0,%1,%2,%3}, {%4,%5,%6,%7}, {%8,%9}, {%0,%1,%2,%3};"
                 : "+f"(c[0]), "+f"(c[1]), "+f"(c[2]), "+f"(c[3])
                 : "r"(a[0]), "r"(a[1]), "r"(a[2]), "r"(a[3]), "r"(b[0]), "r"(b[1]));
}
#define LDSM4(r0, r1, r2, r3, a) \
    asm volatile("ldmatrix.sync.aligned.m8n8.x4.shared.b16 {%0,%1,%2,%3}, [%4];" \
                 : "=r"(r0), "=r"(r1), "=r"(r2), "=r"(r3) : "r"(a))
__device__ __forceinline__ void cp_async16(uint32_t saddr, const void* gptr) {
    asm volatile("cp.async.cg.shared.global [%0], [%1], 16;" :: "r"(saddr), "l"(gptr));
}
#define CP_COMMIT() asm volatile("cp.async.commit_group;" ::: "memory")
#define CP_WAIT1()  asm volatile("cp.async.wait_group 1;" ::: "memory")

__device__ __forceinline__ uint32_t swz(uint32_t off) { return off ^ ((off >> 3) & 0x70); }

// ================= fused prep: router (blocks 0..255) + weight transconv =================
// router: warp-per-token, Wg staged in smem (transposed [e][d]), 32 tokens/block
// transconv: 64x64 fp32->fp16 transpose tiles; W1 blocks 256..8447, W2 8448..16639
__global__ __launch_bounds__(256) void prep_kernel(
    const float* __restrict__ x, const float* __restrict__ Wg,
    const float* __restrict__ W1, const float* __restrict__ W2,
    __half* __restrict__ w1f, __half* __restrict__ w2f)
{
    __shared__ float sh[8192];
    const int bid = blockIdx.x;
    const int tid = threadIdx.x;

    if (bid < 256) {
        // ---- router ----
#pragma unroll
        for (int k = 0; k < 32; k++) {
            int j = k * 256 + tid;
            sh[(j & 7) * 1024 + (j >> 3)] = Wg[j];   // sWg[e][d]
        }
        __syncthreads();
        const int warp = tid >> 5, lane = tid & 31;
#pragma unroll 1
        for (int it = 0; it < 4; it++) {
            int n = bid * 32 + it * 8 + warp;
            const float* xr = x + (size_t)n * DIM;
            float acc[NEXP];
#pragma unroll
            for (int e = 0; e < NEXP; e++) acc[e] = 0.f;
#pragma unroll 8
            for (int i = 0; i < 32; i++) {
                int d = lane + i * 32;
                float xv = xr[d];
#pragma unroll
                for (int e = 0; e < NEXP; e++) acc[e] += xv * sh[e * 1024 + d];
            }
#pragma unroll
            for (int e = 0; e < NEXP; e++) {
#pragma unroll
                for (int o = 16; o > 0; o >>= 1)
                    acc[e] += __shfl_xor_sync(0xffffffffu, acc[e], o);
            }
            if (lane == 0) {
                float m = acc[0]; int bi = 0;
#pragma unroll
                for (int e = 1; e < NEXP; e++) if (acc[e] > m) { m = acc[e]; bi = e; }
                float p[NEXP], s = 0.f;
#pragma unroll
                for (int e = 0; e < NEXP; e++) { p[e] = expf(acc[e] - m); s += p[e]; }
                float inv = 1.f / s;
#pragma unroll
                for (int e = 0; e < NEXP; e++) {
                    p[e] *= inv;
                    g_probs[(size_t)n * NEXP + e] = p[e];
                }
                float lse = m + logf(s);
                g_lse2[n] = lse * lse;
                g_eidx[n] = bi;
                g_eprob[n] = p[bi];
                atomicAdd(&g_counts[bi], 1);
            }
        }
    } else {
        // ---- weight transpose + fp16 convert, 64x64 tiles ----
        int b = bid - 256;
        const float* src; __half* dst; int K, N;
        if (b < 8192) { src = W1; dst = w1f; K = DIM; N = HID; }
        else { b -= 8192; src = W2; dst = w2f; K = HID; N = DIM; }
        int e = b >> 10;
        int rem = b & 1023;
        int tiles_n = N >> 6;
        int nx = rem % tiles_n, ky = rem / tiles_n;
        const float* s = src + (size_t)e * K * N;
        __half* o = dst + (size_t)e * N * K;
        int n0 = nx * 64, k0 = ky * 64;
#pragma unroll
        for (int i = 0; i < 16; i++) {
            int lin = i * 256 + tid;
            int kr = lin >> 6, nc = lin & 63;
            sh[kr * 65 + nc] = s[(size_t)(k0 + kr) * N + n0 + nc];
        }
        __syncthreads();
        int r = tid >> 2, c4 = tid & 3;
        uint32_t w[8];
#pragma unroll
        for (int j = 0; j < 8; j++) {
            float a = sh[(c4 * 16 + 2 * j) * 65 + r];
            float bb = sh[(c4 * 16 + 2 * j + 1) * 65 + r];
            w[j] = pack_h2(a, bb);
        }
        uint4* dp = (uint4*)(o + (size_t)(n0 + r) * K + k0 + c4 * 16);
        dp[0] = make_uint4(w[0], w[1], w[2], w[3]);
        dp[1] = make_uint4(w[4], w[5], w[6], w[7]);
    }
}

// ================= fused pos (blocks 0..7) + reduce (block 8) =================
__global__ __launch_bounds__(1024) void pos_reduce_kernel(float* aux_out) {
    const int tid = threadIdx.x;
    if (blockIdx.x < 8) {
        const int e = blockIdx.x;
        const int lane = tid & 31, wid = tid >> 5;
        __shared__ int wsum[32], wbase[32], sbase;
        int st = 0;
        for (int j = 0; j < e; j++) st += g_counts[j];
        if (tid == 0) sbase = 0;
        __syncthreads();
        for (int n0 = 0; n0 < NTOK; n0 += 1024) {
            int n = n0 + tid;
            bool pred = (g_eidx[n] == e);
            unsigned b = __ballot_sync(0xffffffffu, pred);
            int wpre = __popc(b & ((1u << lane) - 1u));
            if (lane == 0) wsum[wid] = __popc(b);
            __syncthreads();
            if (tid == 0) {
                int r = sbase;
#pragma unroll
                for (int w = 0; w < 32; w++) { wbase[w] = r; r += wsum[w]; }
                sbase = r;
            }
            __syncthreads();
            if (pred) {
                int pos = wbase[wid] + wpre;
                g_sortidx[st + pos] = n;
                if (pos < CAP) { g_slot[n] = pos; g_tok_of_slot[e * CAP + pos] = n; }
                else g_slot[n] = -1;
            }
            __syncthreads();
        }
    } else {
        // reduce: aux loss
        __shared__ float sz[1024];
        __shared__ float sp[NEXP][1024];
        float z = 0.f, p[NEXP];
#pragma unroll
        for (int e = 0; e < NEXP; e++) p[e] = 0.f;
        for (int n = tid; n < NTOK; n += 1024) {
            z += g_lse2[n];
#pragma unroll
            for (int e = 0; e < NEXP; e++) p[e] += g_probs[(size_t)n * NEXP + e];
        }
        sz[tid] = z;
#pragma unroll
        for (int e = 0; e < NEXP; e++) sp[e][tid] = p[e];
        __syncthreads();
        for (int off = 512; off > 0; off >>= 1) {
            if (tid < off) {
                sz[tid] += sz[tid + off];
#pragma unroll
                for (int e = 0; e < NEXP; e++) sp[e][tid] += sp[e][tid + off];
            }
            __syncthreads();
        }
        if (tid == 0) {
            float zloss = sz[0] / (float)NTOK;
            float dot = 0.f;
#pragma unroll
            for (int e = 0; e < NEXP; e++) {
                float fi = (float)g_counts[e] / (float)NTOK;
                float pi = sp[e][0] / (float)NTOK;
                dot += fi * pi;
            }
            if (aux_out) *aux_out = 0.01f * (float)NEXP * dot + 0.001f * zloss;
        }
    }
}

// ================= fused gather (blocks 0..8191) + oscale (8192..8255) =================
__global__ __launch_bounds__(128) void gather_kernel(const float* __restrict__ x) {
    int bid = blockIdx.x;
    if (bid < NEXP * CAP) {
        int e = bid >> 10;
        int slot = bid & (CAP - 1);
        if (slot >= min(g_counts[e], CAP)) return;
        int n = g_tok_of_slot[bid];
        const float4* src = (const float4*)(x + (size_t)n * DIM);
        uint2* dst = (uint2*)(g_xf + (size_t)bid * DIM);
#pragma unroll
        for (int q = 0; q < 2; q++) {
            int i = q * 128 + threadIdx.x;
            float4 v = src[i];
            dst[i] = make_uint2(pack_h2(v.x, v.y), pack_h2(v.z, v.w));
        }
    } else {
        int n = (bid - NEXP * CAP) * 128 + threadIdx.x;
        g_oscale[n] = g_eprob[g_sortidx[n]];
    }
}

// ================= fp16 HMMA grouped GEMM: 128x128 tile, 256 thr, BK=64, 3 stages =================
#define OFF_A  0u
#define OFF_B  16384u
#define ST_SZ  32768u
#define GEMM_SMEM (3u * ST_SZ)

// MODE 0: GELU epilogue -> fp16 hidden; MODE 1: final -> out[token] * oscale
template <int MODE, int K, int NTOT>
__global__ __launch_bounds__(256, 2) void gemm_kernel(
    const __half* __restrict__ Ag, const __half* __restrict__ Bg,
    const float* __restrict__ bias_g,
    __half* __restrict__ outh, float* __restrict__ outf)
{
    extern __shared__ __align__(128) char smem[];
    const uint32_t sbase = smem_u32(smem);
    const int tid  = threadIdx.x;
    const int wid  = tid >> 5;
    const int lane = tid & 31;
    const int wm   = wid & 3;
    const int wn   = wid >> 2;

    const int e    = blockIdx.z;
    const int row0 = blockIdx.y * 128;
    const int col0 = blockIdx.x * 128;

    const __half* A = Ag + (size_t)e * CAP * K + (size_t)row0 * K;
    const __half* B = Bg + (size_t)e * NTOT * K + (size_t)col0 * K;
    const float* bias = bias_g + (size_t)e * NTOT + col0;

    float acc[2][8][4];
#pragma unroll
    for (int mt = 0; mt < 2; mt++)
#pragma unroll
        for (int nt = 0; nt < 8; nt++)
#pragma unroll
            for (int q = 0; q < 4; q++) acc[mt][nt][q] = 0.f;

    const uint32_t aRow  = (uint32_t)(wm * 32 + (lane & 15));
    const uint32_t aBase = aRow * 128 + (uint32_t)((lane >> 4) * 16);
    const uint32_t aMask = (aRow & 7u) << 4;
    const uint32_t bRow  = (uint32_t)(wn * 64 + ((lane >> 4) * 8) + (lane & 7));
    const uint32_t bBase = bRow * 128 + (uint32_t)(((lane >> 3) & 1) * 16);
    const uint32_t bMask = (bRow & 7u) << 4;

    const uint32_t lr = (uint32_t)(tid >> 3);
    const uint32_t ls = (uint32_t)(tid & 7);
    uint32_t sOffA[4], sOffB[4];
    const __half *gA[4], *gB[4];
#pragma unroll
    for (int q = 0; q < 4; q++) {
        uint32_t r = lr + q * 32;
        sOffA[q] = OFF_A + swz(r * 128 + ls * 16);
        sOffB[q] = OFF_B + swz(r * 128 + ls * 16);
        gA[q] = A + (size_t)r * K + ls * 8;
        gB[q] = B + (size_t)r * K + ls * 8;
    }

    auto prefetch = [&](int c, int stage) {
        const uint32_t sb = sbase + (uint32_t)stage * ST_SZ;
        const size_t ko = (size_t)c * 64;
#pragma unroll
        for (int q = 0; q < 4; q++) {
            cp_async16(sb + sOffA[q], gA[q] + ko);
            cp_async16(sb + sOffB[q], gB[q] + ko);
        }
    };

    const int NC = K / 64;
    prefetch(0, 0); CP_COMMIT();
    prefetch(1, 1); CP_COMMIT();

    int stage = 0;
    for (int c = 0; c < NC; c++) {
        CP_WAIT1();
        __syncthreads();
        if (c + 2 < NC) prefetch(c + 2, (stage + 2) % 3);
        CP_COMMIT();

        const uint32_t sb = sbase + (uint32_t)stage * ST_SZ;
#pragma unroll
        for (int kk = 0; kk < 4; kk++) {
            const uint32_t kByte = (uint32_t)(kk * 32);
            uint32_t af[2][4];
#pragma unroll
            for (int mt = 0; mt < 2; mt++) {
                uint32_t ua = (sb + OFF_A + aBase + (uint32_t)(mt * 2048) + kByte) ^ aMask;
                LDSM4(af[mt][0], af[mt][1], af[mt][2], af[mt][3], ua);
            }
#pragma unroll
            for (int bt = 0; bt < 4; bt++) {
                uint32_t ub = (sb + OFF_B + bBase + (uint32_t)(bt * 2048) + kByte) ^ bMask;
                uint32_t r0, r1, r2, r3;
                LDSM4(r0, r1, r2, r3, ub);
                uint32_t bf0[2] = {r0, r1}, bf1[2] = {r2, r3};
#pragma unroll
                for (int mt = 0; mt < 2; mt++) {
                    mma16816(acc[mt][2 * bt + 0], af[mt], bf0);
                    mma16816(acc[mt][2 * bt + 1], af[mt], bf1);
                }
            }
        }
        stage = (stage + 1) % 3;
    }

    // ---- epilogue ----
    const int lrow = lane >> 2;
    const int lcol = (lane & 3) * 2;
    if (MODE == 0) {
        const size_t orow0 = (size_t)e * CAP + row0;
#pragma unroll
        for (int mt = 0; mt < 2; mt++)
#pragma unroll
            for (int half = 0; half < 2; half++) {
                size_t grow = orow0 + wm * 32 + mt * 16 + half * 8 + lrow;
#pragma unroll
                for (int nt = 0; nt < 8; nt++) {
                    int bc = wn * 64 + nt * 8 + lcol;
                    float v0 = acc[mt][nt][half * 2 + 0] + bias[bc];
                    float v1 = acc[mt][nt][half * 2 + 1] + bias[bc + 1];
                    v0 = 0.5f * v0 * (1.0f + erff(v0 * 0.70710678118654752f));
                    v1 = 0.5f * v1 * (1.0f + erff(v1 * 0.70710678118654752f));
                    *(uint32_t*)(outh + grow * NTOT + col0 + bc) = pack_h2(v0, v1);
                }
            }
    } else {
        const int count = min(g_counts[e], CAP);
#pragma unroll
        for (int mt = 0; mt < 2; mt++)
#pragma unroll
            for (int half = 0; half < 2; half++) {
                int lrw = row0 + wm * 32 + mt * 16 + half * 8 + lrow;
                if (lrw < count) {
                    int n = g_tok_of_slot[e * CAP + lrw];
                    float scale = g_oscale[n];
                    float* orow = outf + (size_t)n * NTOT;
#pragma unroll
                    for (int nt = 0; nt < 8; nt++) {
                        int bc = wn * 64 + nt * 8 + lcol;
                        float v0 = (acc[mt][nt][half * 2 + 0] + bias[bc]) * scale;
                        float v1 = (acc[mt][nt][half * 2 + 1] + bias[bc + 1]) * scale;
                        *(float2*)(orow + col0 + bc) = make_float2(v0, v1);
                    }
                }
            }
    }
}

// ================= launch =================
extern "C" void kernel_launch(void* const* d_in, const int* in_sizes, int n_in,
                              void* d_out, int out_size) {
    const float* x  = (const float*)d_in[0];
    const float* Wg = (const float*)d_in[1];
    const float* W1 = (const float*)d_in[2];
    const float* b1 = (const float*)d_in[3];
    const float* W2 = (const float*)d_in[4];
    const float* b2 = (const float*)d_in[5];
    float* out = (float*)d_out;
    float* aux_out = (out_size > NTOK * DIM) ? (out + (size_t)NTOK * DIM) : nullptr;

    cudaFuncSetAttribute(gemm_kernel<0, DIM, HID>,
                         cudaFuncAttributeMaxDynamicSharedMemorySize, GEMM_SMEM);
    cudaFuncSetAttribute(gemm_kernel<1, HID, DIM>,
                         cudaFuncAttributeMaxDynamicSharedMemorySize, GEMM_SMEM);

    __half *w1f, *w2f, *xf, *hf;
    int* counts;
    cudaGetSymbolAddress((void**)&w1f, g_w1f);
    cudaGetSymbolAddress((void**)&w2f, g_w2f);
    cudaGetSymbolAddress((void**)&xf, g_xf);
    cudaGetSymbolAddress((void**)&hf, g_hf);
    cudaGetSymbolAddress((void**)&counts, g_counts);

    cudaMemsetAsync(out, 0, (size_t)out_size * sizeof(float), 0);
    cudaMemsetAsync(counts, 0, NEXP * sizeof(int), 0);

    prep_kernel<<<256 + 2 * 8192, 256>>>(x, Wg, W1, W2, w1f, w2f);
    pos_reduce_kernel<<<9, 1024>>>(aux_out);
    gather_kernel<<<NEXP * CAP + NTOK / 128, 128>>>(x);

    dim3 g1(HID / 128, CAP / 128, NEXP);   // 32 x 8 x 8
    gemm_kernel<0, DIM, HID><<<g1, 256, GEMM_SMEM>>>(xf, w1f, b1, hf, nullptr);

    dim3 g2(DIM / 128, CAP / 128, NEXP);   // 8 x 8 x 8
    gemm_kernel<1, HID, DIM><<<g2, 256, GEMM_SMEM>>>(hf, w2f, b2, nullptr, out);
}

// round 13
// speedup vs baseline: 6.5719x; 1.0290x over previous
#include <cuda_runtime.h>
#include <cuda_fp16.h>
#include <math.h>
#include <stdint.h>

#define NTOK 8192
#define DIM  1024
#define NEXP 8
#define HID  4096
#define CAP  1024

// ================= scratch =================
__device__ __half g_xf[(size_t)NTOK * DIM];
__device__ __half g_hf[(size_t)NTOK * HID];
__device__ __half g_w1f[(size_t)NEXP * HID * DIM];  // transposed [E][H][D]
__device__ __half g_w2f[(size_t)NEXP * DIM * HID];  // transposed [E][D][H]
__device__ float g_probs[(size_t)NTOK * NEXP];
__device__ float g_lse2[NTOK];
__device__ float g_eprob[NTOK];
__device__ float g_oscale[NTOK];
__device__ int   g_eidx[NTOK];
__device__ int   g_slot[NTOK];
__device__ int   g_sortidx[NTOK];
__device__ int   g_tok_of_slot[NEXP * CAP];
__device__ int   g_counts[NEXP];

__device__ __forceinline__ uint32_t smem_u32(const void* p) {
    uint32_t a;
    asm("{ .reg .u64 t; cvta.to.shared.u64 t, %1; cvt.u32.u64 %0, t; }" : "=r"(a) : "l"(p));
    return a;
}
__device__ __forceinline__ uint32_t pack_h2(float a, float b) {
    __half2 h = __floats2half2_rn(a, b);
    return *(uint32_t*)&h;
}

// ---- PTX: mma / ldmatrix / cp.async ----
__device__ __forceinline__ void mma16816(float* c, const uint32_t* a, const uint32_t* b) {
    asm volatile("mma.sync.aligned.m16n8k16.row.col.f32.f16.f16.f32 "
                 "{%0,%1,%2,%3}, {%4,%5,%6,%7}, {%8,%9}, {%0,%1,%2,%3};"
                 : "+f"(c[0]), "+f"(c[1]), "+f"(c[2]), "+f"(c[3])
                 : "r"(a[0]), "r"(a[1]), "r"(a[2]), "r"(a[3]), "r"(b[0]), "r"(b[1]));
}
#define LDSM4(r0, r1, r2, r3, a) \
    asm volatile("ldmatrix.sync.aligned.m8n8.x4.shared.b16 {%0,%1,%2,%3}, [%4];" \
                 : "=r"(r0), "=r"(r1), "=r"(r2), "=r"(r3) : "r"(a))
__device__ __forceinline__ void cp_async16(uint32_t saddr, const void* gptr) {
    asm volatile("cp.async.cg.shared.global [%0], [%1], 16;" :: "r"(saddr), "l"(gptr));
}
#define CP_COMMIT() asm volatile("cp.async.commit_group;" ::: "memory")
#define CP_WAIT1()  asm volatile("cp.async.wait_group 1;" ::: "memory")

__device__ __forceinline__ uint32_t swz(uint32_t off) { return off ^ ((off >> 3) & 0x70); }

// ================= fused prep: router (blocks 0..255) + weight transconv =================
__global__ __launch_bounds__(256) void prep_kernel(
    const float* __restrict__ x, const float* __restrict__ Wg,
    const float* __restrict__ W1, const float* __restrict__ W2,
    __half* __restrict__ w1f, __half* __restrict__ w2f)
{
    __shared__ float sh[8192];
    const int bid = blockIdx.x;
    const int tid = threadIdx.x;

    if (bid < 256) {
        // ---- router ----
#pragma unroll
        for (int k = 0; k < 32; k++) {
            int j = k * 256 + tid;
            sh[(j & 7) * 1024 + (j >> 3)] = Wg[j];   // sWg[e][d]
        }
        __syncthreads();
        const int warp = tid >> 5, lane = tid & 31;
#pragma unroll 1
        for (int it = 0; it < 4; it++) {
            int n = bid * 32 + it * 8 + warp;
            const float* xr = x + (size_t)n * DIM;
            float acc[NEXP];
#pragma unroll
            for (int e = 0; e < NEXP; e++) acc[e] = 0.f;
#pragma unroll 8
            for (int i = 0; i < 32; i++) {
                int d = lane + i * 32;
                float xv = xr[d];
#pragma unroll
                for (int e = 0; e < NEXP; e++) acc[e] += xv * sh[e * 1024 + d];
            }
#pragma unroll
            for (int e = 0; e < NEXP; e++) {
#pragma unroll
                for (int o = 16; o > 0; o >>= 1)
                    acc[e] += __shfl_xor_sync(0xffffffffu, acc[e], o);
            }
            if (lane == 0) {
                float m = acc[0]; int bi = 0;
#pragma unroll
                for (int e = 1; e < NEXP; e++) if (acc[e] > m) { m = acc[e]; bi = e; }
                float p[NEXP], s = 0.f;
#pragma unroll
                for (int e = 0; e < NEXP; e++) { p[e] = expf(acc[e] - m); s += p[e]; }
                float inv = 1.f / s;
#pragma unroll
                for (int e = 0; e < NEXP; e++) {
                    p[e] *= inv;
                    g_probs[(size_t)n * NEXP + e] = p[e];
                }
                float lse = m + logf(s);
                g_lse2[n] = lse * lse;
                g_eidx[n] = bi;
                g_eprob[n] = p[bi];
                atomicAdd(&g_counts[bi], 1);
            }
        }
    } else {
        // ---- weight transpose + fp16 convert, 64x64 tiles ----
        int b = bid - 256;
        const float* src; __half* dst; int K, N;
        if (b < 8192) { src = W1; dst = w1f; K = DIM; N = HID; }
        else { b -= 8192; src = W2; dst = w2f; K = HID; N = DIM; }
        int e = b >> 10;
        int rem = b & 1023;
        int tiles_n = N >> 6;
        int nx = rem % tiles_n, ky = rem / tiles_n;
        const float* s = src + (size_t)e * K * N;
        __half* o = dst + (size_t)e * N * K;
        int n0 = nx * 64, k0 = ky * 64;
#pragma unroll
        for (int i = 0; i < 16; i++) {
            int lin = i * 256 + tid;
            int kr = lin >> 6, nc = lin & 63;
            sh[kr * 65 + nc] = s[(size_t)(k0 + kr) * N + n0 + nc];
        }
        __syncthreads();
        int r = tid >> 2, c4 = tid & 3;
        uint32_t w[8];
#pragma unroll
        for (int j = 0; j < 8; j++) {
            float a = sh[(c4 * 16 + 2 * j) * 65 + r];
            float bb = sh[(c4 * 16 + 2 * j + 1) * 65 + r];
            w[j] = pack_h2(a, bb);
        }
        uint4* dp = (uint4*)(o + (size_t)(n0 + r) * K + k0 + c4 * 16);
        dp[0] = make_uint4(w[0], w[1], w[2], w[3]);
        dp[1] = make_uint4(w[4], w[5], w[6], w[7]);
    }
}

// ================= fused pos (blocks 0..7) + reduce (block 8) =================
__global__ __launch_bounds__(1024) void pos_reduce_kernel(float* aux_out) {
    const int tid = threadIdx.x;
    if (blockIdx.x < 8) {
        const int e = blockIdx.x;
        const int lane = tid & 31, wid = tid >> 5;
        __shared__ int wsum[32], wbase[32], sbase;
        int st = 0;
        for (int j = 0; j < e; j++) st += g_counts[j];
        if (tid == 0) sbase = 0;
        __syncthreads();
        for (int n0 = 0; n0 < NTOK; n0 += 1024) {
            int n = n0 + tid;
            bool pred = (g_eidx[n] == e);
            unsigned b = __ballot_sync(0xffffffffu, pred);
            int wpre = __popc(b & ((1u << lane) - 1u));
            if (lane == 0) wsum[wid] = __popc(b);
            __syncthreads();
            if (tid == 0) {
                int r = sbase;
#pragma unroll
                for (int w = 0; w < 32; w++) { wbase[w] = r; r += wsum[w]; }
                sbase = r;
            }
            __syncthreads();
            if (pred) {
                int pos = wbase[wid] + wpre;
                g_sortidx[st + pos] = n;
                if (pos < CAP) { g_slot[n] = pos; g_tok_of_slot[e * CAP + pos] = n; }
                else g_slot[n] = -1;
            }
            __syncthreads();
        }
    } else {
        __shared__ float sz[1024];
        __shared__ float sp[NEXP][1024];
        float z = 0.f, p[NEXP];
#pragma unroll
        for (int e = 0; e < NEXP; e++) p[e] = 0.f;
        for (int n = tid; n < NTOK; n += 1024) {
            z += g_lse2[n];
#pragma unroll
            for (int e = 0; e < NEXP; e++) p[e] += g_probs[(size_t)n * NEXP + e];
        }
        sz[tid] = z;
#pragma unroll
        for (int e = 0; e < NEXP; e++) sp[e][tid] = p[e];
        __syncthreads();
        for (int off = 512; off > 0; off >>= 1) {
            if (tid < off) {
                sz[tid] += sz[tid + off];
#pragma unroll
                for (int e = 0; e < NEXP; e++) sp[e][tid] += sp[e][tid + off];
            }
            __syncthreads();
        }
        if (tid == 0) {
            float zloss = sz[0] / (float)NTOK;
            float dot = 0.f;
#pragma unroll
            for (int e = 0; e < NEXP; e++) {
                float fi = (float)g_counts[e] / (float)NTOK;
                float pi = sp[e][0] / (float)NTOK;
                dot += fi * pi;
            }
            if (aux_out) *aux_out = 0.01f * (float)NEXP * dot + 0.001f * zloss;
        }
    }
}

// ================= fused gather (blocks 0..8191) + oscale (8192..8255) =================
__global__ __launch_bounds__(128) void gather_kernel(const float* __restrict__ x) {
    int bid = blockIdx.x;
    if (bid < NEXP * CAP) {
        int e = bid >> 10;
        int slot = bid & (CAP - 1);
        if (slot >= min(g_counts[e], CAP)) return;
        int n = g_tok_of_slot[bid];
        const float4* src = (const float4*)(x + (size_t)n * DIM);
        uint2* dst = (uint2*)(g_xf + (size_t)bid * DIM);
#pragma unroll
        for (int q = 0; q < 2; q++) {
            int i = q * 128 + threadIdx.x;
            float4 v = src[i];
            dst[i] = make_uint2(pack_h2(v.x, v.y), pack_h2(v.z, v.w));
        }
    } else {
        int n = (bid - NEXP * CAP) * 128 + threadIdx.x;
        g_oscale[n] = g_eprob[g_sortidx[n]];
    }
}

// ================= fp16 HMMA grouped GEMM: 128x128 tile, 256 thr, BK=64, 2 stages =================
#define OFF_A  0u
#define OFF_B  16384u
#define ST_SZ  32768u
#define GEMM_SMEM (2u * ST_SZ)

// MODE 0: GELU epilogue -> fp16 hidden; MODE 1: final -> out[token] * oscale
template <int MODE, int K, int NTOT>
__global__ __launch_bounds__(256, 2) void gemm_kernel(
    const __half* __restrict__ Ag, const __half* __restrict__ Bg,
    const float* __restrict__ bias_g,
    __half* __restrict__ outh, float* __restrict__ outf)
{
    extern __shared__ __align__(128) char smem[];
    const uint32_t sbase = smem_u32(smem);
    const int tid  = threadIdx.x;
    const int wid  = tid >> 5;
    const int lane = tid & 31;
    const int wm   = wid & 3;
    const int wn   = wid >> 2;

    const int e    = blockIdx.z;
    const int row0 = blockIdx.y * 128;
    const int col0 = blockIdx.x * 128;

    const __half* A = Ag + (size_t)e * CAP * K + (size_t)row0 * K;
    const __half* B = Bg + (size_t)e * NTOT * K + (size_t)col0 * K;
    const float* bias = bias_g + (size_t)e * NTOT + col0;

    float acc[2][8][4];
#pragma unroll
    for (int mt = 0; mt < 2; mt++)
#pragma unroll
        for (int nt = 0; nt < 8; nt++)
#pragma unroll
            for (int q = 0; q < 4; q++) acc[mt][nt][q] = 0.f;

    const uint32_t aRow  = (uint32_t)(wm * 32 + (lane & 15));
    const uint32_t aBase = aRow * 128 + (uint32_t)((lane >> 4) * 16);
    const uint32_t aMask = (aRow & 7u) << 4;
    const uint32_t bRow  = (uint32_t)(wn * 64 + ((lane >> 4) * 8) + (lane & 7));
    const uint32_t bBase = bRow * 128 + (uint32_t)(((lane >> 3) & 1) * 16);
    const uint32_t bMask = (bRow & 7u) << 4;

    // loader: single base + compile-time offsets (q*32 rows -> +q*4096 smem, +q*32*K gmem)
    const uint32_t lr = (uint32_t)(tid >> 3);      // 0..31
    const uint32_t ls = (uint32_t)(tid & 7);       // 0..7
    const uint32_t sOff0 = swz(lr * 128 + ls * 16);
    const __half* gA0 = A + (size_t)lr * K + ls * 8;
    const __half* gB0 = B + (size_t)lr * K + ls * 8;

    auto prefetch = [&](int c, int stage) {
        const uint32_t sb = sbase + (uint32_t)stage * ST_SZ;
        const size_t ko = (size_t)c * 64;
#pragma unroll
        for (int q = 0; q < 4; q++) {
            cp_async16(sb + OFF_A + sOff0 + (uint32_t)(q * 4096), gA0 + (size_t)(q * 32) * K + ko);
            cp_async16(sb + OFF_B + sOff0 + (uint32_t)(q * 4096), gB0 + (size_t)(q * 32) * K + ko);
        }
    };

    const int NC = K / 64;
    prefetch(0, 0); CP_COMMIT();

    for (int c = 0; c < NC; c++) {
        __syncthreads();                       // all warps done reading stage (c+1)&1
        if (c + 1 < NC) prefetch(c + 1, (c + 1) & 1);
        CP_COMMIT();
        CP_WAIT1();                            // stage c&1 resident
        __syncthreads();

        const uint32_t sb = sbase + (uint32_t)(c & 1) * ST_SZ;
#pragma unroll
        for (int kk = 0; kk < 4; kk++) {
            const uint32_t kByte = (uint32_t)(kk * 32);
            uint32_t af[2][4];
#pragma unroll
            for (int mt = 0; mt < 2; mt++) {
                uint32_t ua = (sb + OFF_A + aBase + (uint32_t)(mt * 2048) + kByte) ^ aMask;
                LDSM4(af[mt][0], af[mt][1], af[mt][2], af[mt][3], ua);
            }
#pragma unroll
            for (int bt = 0; bt < 4; bt++) {
                uint32_t ub = (sb + OFF_B + bBase + (uint32_t)(bt * 2048) + kByte) ^ bMask;
                uint32_t r0, r1, r2, r3;
                LDSM4(r0, r1, r2, r3, ub);
                uint32_t bf0[2] = {r0, r1}, bf1[2] = {r2, r3};
#pragma unroll
                for (int mt = 0; mt < 2; mt++) {
                    mma16816(acc[mt][2 * bt + 0], af[mt], bf0);
                    mma16816(acc[mt][2 * bt + 1], af[mt], bf1);
                }
            }
        }
    }

    // ---- epilogue ----
    const int lrow = lane >> 2;
    const int lcol = (lane & 3) * 2;
    if (MODE == 0) {
        const size_t orow0 = (size_t)e * CAP + row0;
#pragma unroll
        for (int mt = 0; mt < 2; mt++)
#pragma unroll
            for (int half = 0; half < 2; half++) {
                size_t grow = orow0 + wm * 32 + mt * 16 + half * 8 + lrow;
#pragma unroll
                for (int nt = 0; nt < 8; nt++) {
                    int bc = wn * 64 + nt * 8 + lcol;
                    float v0 = acc[mt][nt][half * 2 + 0] + bias[bc];
                    float v1 = acc[mt][nt][half * 2 + 1] + bias[bc + 1];
                    v0 = 0.5f * v0 * (1.0f + erff(v0 * 0.70710678118654752f));
                    v1 = 0.5f * v1 * (1.0f + erff(v1 * 0.70710678118654752f));
                    *(uint32_t*)(outh + grow * NTOT + col0 + bc) = pack_h2(v0, v1);
                }
            }
    } else {
        const int count = min(g_counts[e], CAP);
#pragma unroll
        for (int mt = 0; mt < 2; mt++)
#pragma unroll
            for (int half = 0; half < 2; half++) {
                int lrw = row0 + wm * 32 + mt * 16 + half * 8 + lrow;
                if (lrw < count) {
                    int n = g_tok_of_slot[e * CAP + lrw];
                    float scale = g_oscale[n];
                    float* orow = outf + (size_t)n * NTOT;
#pragma unroll
                    for (int nt = 0; nt < 8; nt++) {
                        int bc = wn * 64 + nt * 8 + lcol;
                        float v0 = (acc[mt][nt][half * 2 + 0] + bias[bc]) * scale;
                        float v1 = (acc[mt][nt][half * 2 + 1] + bias[bc + 1]) * scale;
                        *(float2*)(orow + col0 + bc) = make_float2(v0, v1);
                    }
                }
            }
    }
}

// ================= launch =================
extern "C" void kernel_launch(void* const* d_in, const int* in_sizes, int n_in,
                              void* d_out, int out_size) {
    const float* x  = (const float*)d_in[0];
    const float* Wg = (const float*)d_in[1];
    const float* W1 = (const float*)d_in[2];
    const float* b1 = (const float*)d_in[3];
    const float* W2 = (const float*)d_in[4];
    const float* b2 = (const float*)d_in[5];
    float* out = (float*)d_out;
    float* aux_out = (out_size > NTOK * DIM) ? (out + (size_t)NTOK * DIM) : nullptr;

    cudaFuncSetAttribute(gemm_kernel<0, DIM, HID>,
                         cudaFuncAttributeMaxDynamicSharedMemorySize, GEMM_SMEM);
    cudaFuncSetAttribute(gemm_kernel<1, HID, DIM>,
                         cudaFuncAttributeMaxDynamicSharedMemorySize, GEMM_SMEM);

    __half *w1f, *w2f, *xf, *hf;
    int* counts;
    cudaGetSymbolAddress((void**)&w1f, g_w1f);
    cudaGetSymbolAddress((void**)&w2f, g_w2f);
    cudaGetSymbolAddress((void**)&xf, g_xf);
    cudaGetSymbolAddress((void**)&hf, g_hf);
    cudaGetSymbolAddress((void**)&counts, g_counts);

    cudaMemsetAsync(out, 0, (size_t)out_size * sizeof(float), 0);
    cudaMemsetAsync(counts, 0, NEXP * sizeof(int), 0);

    prep_kernel<<<256 + 2 * 8192, 256>>>(x, Wg, W1, W2, w1f, w2f);
    pos_reduce_kernel<<<9, 1024>>>(aux_out);
    gather_kernel<<<NEXP * CAP + NTOK / 128, 128>>>(x);

    dim3 g1(HID / 128, CAP / 128, NEXP);   // 32 x 8 x 8
    gemm_kernel<0, DIM, HID><<<g1, 256, GEMM_SMEM>>>(xf, w1f, b1, hf, nullptr);

    dim3 g2(DIM / 128, CAP / 128, NEXP);   // 8 x 8 x 8
    gemm_kernel<1, HID, DIM><<<g2, 256, GEMM_SMEM>>>(hf, w2f, b2, nullptr, out);
}